// round 5
// baseline (speedup 1.0000x reference)
#include <cuda_runtime.h>
#include <math.h>
#include <stdint.h>

#define NN 4096
#define HEADS 8
#define DH 128
#define MAXMASK 2048
#define ATT_SCALE 0.03125f  // 1024^-0.5

// ---------------- scratch ----------------
__device__ float g_xr [(size_t)8192*1024];   // x rounded to tf32
__device__ float g_q  [(size_t)16*NN*DH];    // [bh][n][d]
__device__ float g_k  [(size_t)16*NN*DH];    // [bh][n][d]
__device__ float g_vT [(size_t)16*DH*NN];    // [bh][d][n]
__device__ float g_att[(size_t)8192*1024];   // [b*n][dim]
__device__ float g_wqkvT[(size_t)3072*1024]; // W_qkv^T (tf32-rounded)
__device__ float g_woutT[(size_t)1024*1024]; // W_out^T (tf32-rounded)

// ---------------- helpers ----------------
__device__ __forceinline__ uint32_t smem_u32(const void* p) {
    uint32_t a;
    asm("{ .reg .u64 t; cvta.to.shared.u64 t, %1; cvt.u32.u64 %0, t; }"
        : "=r"(a) : "l"(p));
    return a;
}
__device__ __forceinline__ float rnd_tf32(float x) {
    uint32_t r;
    asm("cvt.rna.tf32.f32 %0, %1;" : "=r"(r) : "f"(x));
    return __uint_as_float(r);
}
__device__ __forceinline__ void cp16(uint32_t sdst, const void* gsrc) {
    asm volatile("cp.async.cg.shared.global [%0], [%1], 16;"
                 :: "r"(sdst), "l"(gsrc) : "memory");
}
#define CP_COMMIT() asm volatile("cp.async.commit_group;" ::: "memory")
#define CP_WAIT(n)  asm volatile("cp.async.wait_group %0;" :: "n"(n) : "memory")

__device__ __forceinline__ void ldsm4(uint32_t* r, uint32_t saddr) {
    asm volatile("ldmatrix.sync.aligned.m8n8.x4.shared.b16 {%0,%1,%2,%3}, [%4];"
        : "=r"(r[0]), "=r"(r[1]), "=r"(r[2]), "=r"(r[3]) : "r"(saddr));
}
__device__ __forceinline__ void mma8(float* d, const uint32_t* a, const uint32_t* b) {
    asm volatile(
        "mma.sync.aligned.m16n8k8.row.col.f32.tf32.tf32.f32 "
        "{%0,%1,%2,%3}, {%4,%5,%6,%7}, {%8,%9}, {%0,%1,%2,%3};"
        : "+f"(d[0]), "+f"(d[1]), "+f"(d[2]), "+f"(d[3])
        : "r"(a[0]), "r"(a[1]), "r"(a[2]), "r"(a[3]), "r"(b[0]), "r"(b[1]));
}
__device__ __forceinline__ uint32_t swz(int row, int slot, int rowb) {
    return (uint32_t)(row * rowb + ((slot ^ (row & 7)) << 4));
}

// ---------------- pre-round x to tf32 ----------------
__global__ void round_x(const float* __restrict__ in, float* __restrict__ outp)
{
    size_t i = ((size_t)blockIdx.x * blockDim.x + threadIdx.x) * 4;
    float4 v = *(const float4*)(in + i);
    v.x = rnd_tf32(v.x); v.y = rnd_tf32(v.y);
    v.z = rnd_tf32(v.z); v.w = rnd_tf32(v.w);
    *(float4*)(outp + i) = v;
}

// ---------------- weight transpose + tf32 round: in[R][C] -> out[C][R] -----
__global__ void transpose_k(const float* __restrict__ in, float* __restrict__ outp,
                            int R, int C)
{
    __shared__ float t[32][33];
    int bx = blockIdx.x * 32, by = blockIdx.y * 32;
    int tx = threadIdx.x, ty = threadIdx.y;  // 32 x 8
#pragma unroll
    for (int i = 0; i < 32; i += 8)
        t[ty + i][tx] = in[(size_t)(by + ty + i) * C + bx + tx];
    __syncthreads();
#pragma unroll
    for (int i = 0; i < 32; i += 8)
        outp[(size_t)(bx + ty + i) * R + by + tx] = rnd_tf32(t[tx][ty + i]);
}

// ================= GEMM: C[M x Ncols] = A[M x 1024] * Bt[Ncols x 1024]^T =======
#define GEMM_SMEM 65536
template<int MODE>
__global__ __launch_bounds__(256, 2) void mma_gemm(
    const float* __restrict__ A, const float* __restrict__ Bt,
    const float* __restrict__ bias, float* __restrict__ out)
{
    extern __shared__ char sm[];
    const uint32_t sb = smem_u32(sm);
    const int tid = threadIdx.x, lane = tid & 31, wid = tid >> 5;
    const int wm = wid >> 2, wn = wid & 3;
    const int g = lane >> 2, l4 = lane & 3;
    const int m0 = blockIdx.y * 128, col0 = blockIdx.x * 128;

    const int arow_l = (lane & 7) + ((lane >> 3) & 1) * 8;
    const int asel = (lane >> 4) & 1;
    const int brow_l = (lane & 7) + ((lane >> 4) & 1) * 8;
    const int bsel = (lane >> 3) & 1;

    float acc[4][4][4];
#pragma unroll
    for (int mt = 0; mt < 4; mt++)
#pragma unroll
        for (int nt = 0; nt < 4; nt++)
#pragma unroll
            for (int r = 0; r < 4; r++) acc[mt][nt][r] = 0.f;

    auto fill = [&](int buf, int k0) {
#pragma unroll
        for (int i = 0; i < 4; i++) {
            int p = tid + i * 256;
            int r = p >> 3, s = p & 7;
            cp16(sb + buf * 16384 + swz(r, s, 128),
                 A + (size_t)(m0 + r) * 1024 + k0 + s * 4);
        }
#pragma unroll
        for (int i = 0; i < 4; i++) {
            int p = tid + i * 256;
            int r = p >> 3, s = p & 7;
            cp16(sb + 32768 + buf * 16384 + swz(r, s, 128),
                 Bt + (size_t)(col0 + r) * 1024 + k0 + s * 4);
        }
    };

    fill(0, 0);
    CP_COMMIT();

    for (int kb = 0; kb < 32; kb++) {
        if (kb < 31) { fill((kb + 1) & 1, (kb + 1) * 32); CP_COMMIT(); CP_WAIT(1); }
        else CP_WAIT(0);
        __syncthreads();
        const uint32_t ab = sb + (kb & 1) * 16384;
        const uint32_t bb = sb + 32768 + (kb & 1) * 16384;
#pragma unroll
        for (int ks = 0; ks < 4; ks++) {
            uint32_t a[4][4], b[2][4];
#pragma unroll
            for (int mt = 0; mt < 4; mt++) {
                int row = wm * 64 + mt * 16 + arow_l;
                ldsm4(a[mt], ab + swz(row, 2 * ks + asel, 128));
            }
#pragma unroll
            for (int pr = 0; pr < 2; pr++) {
                int row = wn * 32 + pr * 16 + brow_l;
                ldsm4(b[pr], bb + swz(row, 2 * ks + bsel, 128));
            }
#pragma unroll
            for (int mt = 0; mt < 4; mt++)
#pragma unroll
                for (int nt = 0; nt < 4; nt++)
                    mma8(acc[mt][nt], a[mt], &b[nt >> 1][(nt & 1) * 2]);
        }
        __syncthreads();
    }

    if (MODE == 0) {
        const int which = col0 >> 10;          // 0=q 1=k 2=v
        const int h = (col0 & 1023) >> 7;
#pragma unroll
        for (int mt = 0; mt < 4; mt++)
#pragma unroll
            for (int nt = 0; nt < 4; nt++) {
                int col = col0 + wn * 32 + nt * 8 + 2 * l4;
                int dd = col & 127;
#pragma unroll
                for (int hf = 0; hf < 2; hf++) {
                    int gr = m0 + wm * 64 + mt * 16 + g + 8 * hf;
                    int bb2 = gr >> 12, n = gr & 4095;
                    int bh = bb2 * HEADS + h;
                    float c0 = rnd_tf32(acc[mt][nt][hf * 2]);
                    float c1 = rnd_tf32(acc[mt][nt][hf * 2 + 1]);
                    if (which == 0)
                        *(float2*)(g_q + ((size_t)bh * NN + n) * DH + dd) = make_float2(c0, c1);
                    else if (which == 1)
                        *(float2*)(g_k + ((size_t)bh * NN + n) * DH + dd) = make_float2(c0, c1);
                    else {
                        float* dst = g_vT + ((size_t)bh * DH + dd) * NN + n;
                        dst[0] = c0; dst[NN] = c1;
                    }
                }
            }
    } else {
#pragma unroll
        for (int mt = 0; mt < 4; mt++)
#pragma unroll
            for (int nt = 0; nt < 4; nt++) {
                int col = col0 + wn * 32 + nt * 8 + 2 * l4;
                float2 bv = *(const float2*)(bias + col);
#pragma unroll
                for (int hf = 0; hf < 2; hf++) {
                    int gr = m0 + wm * 64 + mt * 16 + g + 8 * hf;
                    *(float2*)(out + (size_t)gr * 1024 + col) =
                        make_float2(acc[mt][nt][hf * 2] + bv.x,
                                    acc[mt][nt][hf * 2 + 1] + bv.y);
                }
            }
    }
}

// ================= Flash attention (512 threads, 16 warps) =================
// i-tile 128, j-tile 64. Warps: wm = wid&7 (16 rows each), wg = wid>>3.
// S: warp = 16 rows x 32 j (1 m-tile x 4 n-tiles, k=128).
// PV: warp = 16 rows x 64 d (1 m-tile x 8 n-tiles, k=64).
#define QS_OFF   0          // 128 x 512B = 64KB
#define K_OFF(b) (65536 + (b) * 32768)   // 64 x 512B each
#define VS_OFF   131072     // 128 x 256B = 32KB   (V^T: rows=d, cols=j)
#define PS_OFF   163840     // 128 x 256B = 32KB   (P: rows=i, cols=j)
#define REDM_OFF 196608     // float[128][2]
#define REDS_OFF 197632     // float[128][2]
#define ATT_SMEM 198656

__global__ __launch_bounds__(512) void attn_kernel(const int* __restrict__ mask)
{
    extern __shared__ char sm[];
    const uint32_t sb = smem_u32(sm);
    float (*redm)[2] = (float(*)[2])(sm + REDM_OFF);
    float (*reds)[2] = (float(*)[2])(sm + REDS_OFF);

    const int tid = threadIdx.x, lane = tid & 31, wid = tid >> 5;
    const int wm = wid & 7, wg = wid >> 3;
    const int g = lane >> 2, l4 = lane & 3;
    const int i0 = blockIdx.x * 128;
    const int bh = blockIdx.y;

    const float* qP  = g_q  + (size_t)bh * NN * DH;
    const float* kP  = g_k  + (size_t)bh * NN * DH;
    const float* vTP = g_vT + (size_t)bh * DH * NN;

    const int arow_l = (lane & 7) + ((lane >> 3) & 1) * 8;
    const int asel = (lane >> 4) & 1;
    const int brow_l = (lane & 7) + ((lane >> 4) & 1) * 8;
    const int bsel = (lane >> 3) & 1;

    // Q fill (group 1): 128 rows x 32 slots
#pragma unroll
    for (int i = 0; i < 8; i++) {
        int p = tid + i * 512;
        int r = p >> 5, s = p & 31;
        cp16(sb + QS_OFF + swz(r, s, 512), qP + (size_t)(i0 + r) * DH + s * 4);
    }
    CP_COMMIT();
    // K(0) fill (group 2): 64 rows x 32 slots
#pragma unroll
    for (int i = 0; i < 4; i++) {
        int p = tid + i * 512;
        int r = p >> 5, s = p & 31;
        cp16(sb + K_OFF(0) + swz(r, s, 512), kP + (size_t)r * DH + s * 4);
    }
    CP_COMMIT();

    float oacc[8][4];
#pragma unroll
    for (int nt = 0; nt < 8; nt++)
#pragma unroll
        for (int r = 0; r < 4; r++) oacc[nt][r] = 0.f;
    float mreg[2] = {-1e30f, -1e30f};
    float lreg[2] = {0.f, 0.f};

    for (int jt = 0; jt < 64; jt++) {
        const int j0 = jt * 64;
        __syncthreads();   // prev PV done with V / P buffers

        // V(jt) fill: 128 d-rows x 16 slots
#pragma unroll
        for (int i = 0; i < 4; i++) {
            int p = tid + i * 512;
            int r = p >> 4, s = p & 15;
            cp16(sb + VS_OFF + swz(r, s, 256), vTP + (size_t)r * NN + j0 + s * 4);
        }
        CP_COMMIT();
        CP_WAIT(1);        // K(jt) complete; V may be pending
        __syncthreads();

        // ---- S = Q K^T ----
        float sacc[4][4];
#pragma unroll
        for (int nt = 0; nt < 4; nt++)
#pragma unroll
            for (int r = 0; r < 4; r++) sacc[nt][r] = 0.f;

        const uint32_t kb = sb + K_OFF(jt & 1);
#pragma unroll
        for (int ks = 0; ks < 16; ks++) {
            uint32_t a[4], b[2][4];
            ldsm4(a, sb + QS_OFF + swz(wm * 16 + arow_l, 2 * ks + asel, 512));
#pragma unroll
            for (int pr = 0; pr < 2; pr++)
                ldsm4(b[pr], kb + swz(wg * 32 + pr * 16 + brow_l, 2 * ks + bsel, 512));
#pragma unroll
            for (int nt = 0; nt < 4; nt++)
                mma8(sacc[nt], a, &b[nt >> 1][(nt & 1) * 2]);
        }

        // prefetch K(jt+1)
        if (jt < 63) {
            const float* kn = kP + (size_t)(j0 + 64) * DH;
#pragma unroll
            for (int i = 0; i < 4; i++) {
                int p = tid + i * 512;
                int r = p >> 5, s = p & 31;
                cp16(sb + K_OFF((jt + 1) & 1) + swz(r, s, 512),
                     kn + (size_t)r * DH + s * 4);
            }
            CP_COMMIT();
        }

        // ---- scale + mask ----
#pragma unroll
        for (int nt = 0; nt < 4; nt++)
#pragma unroll
            for (int r = 0; r < 4; r++) sacc[nt][r] *= ATT_SCALE;
        if (i0 < MAXMASK && j0 < MAXMASK) {
#pragma unroll
            for (int hf = 0; hf < 2; hf++) {
                int gi = i0 + wm * 16 + g + 8 * hf;
                const int* mp = mask + (size_t)gi * MAXMASK + j0 + wg * 32;
#pragma unroll
                for (int nt = 0; nt < 4; nt++) {
                    int2 mv = *(const int2*)(mp + nt * 8 + 2 * l4);
                    if (mv.x == 0) sacc[nt][hf * 2]     = -INFINITY;
                    if (mv.y == 0) sacc[nt][hf * 2 + 1] = -INFINITY;
                }
            }
        }

        // ---- softmax stage 1: per-row partial max ----
#pragma unroll
        for (int hf = 0; hf < 2; hf++) {
            float pm = -INFINITY;
#pragma unroll
            for (int nt = 0; nt < 4; nt++)
                pm = fmaxf(pm, fmaxf(sacc[nt][hf * 2], sacc[nt][hf * 2 + 1]));
            pm = fmaxf(pm, __shfl_xor_sync(0xffffffffu, pm, 1));
            pm = fmaxf(pm, __shfl_xor_sync(0xffffffffu, pm, 2));
            if (l4 == 0) redm[wm * 16 + g + 8 * hf][wg] = pm;
        }
        __syncthreads();

        // ---- softmax stage 2: combine, exp, partial sums, P store ----
        float corr[2];
#pragma unroll
        for (int hf = 0; hf < 2; hf++) {
            int lr = wm * 16 + g + 8 * hf;
            float nm = fmaxf(fmaxf(redm[lr][0], redm[lr][1]), mreg[hf]);
            float mc = fmaxf(nm, -1e30f);
            corr[hf] = __expf(mreg[hf] - mc);
            mreg[hf] = mc;
            float rs = 0.f;
#pragma unroll
            for (int nt = 0; nt < 4; nt++) {
                float p0 = __expf(sacc[nt][hf * 2]     - mc);
                float p1 = __expf(sacc[nt][hf * 2 + 1] - mc);
                rs += p0 + p1;
                int cslot = wg * 8 + nt * 2 + (l4 >> 1);
                *(float2*)(sm + PS_OFF + lr * 256
                           + ((cslot ^ (lr & 7)) << 4) + (l4 & 1) * 8) =
                    make_float2(rnd_tf32(p0), rnd_tf32(p1));
            }
            rs += __shfl_xor_sync(0xffffffffu, rs, 1);
            rs += __shfl_xor_sync(0xffffffffu, rs, 2);
            if (l4 == 0) reds[lr][wg] = rs;
        }
        if (jt < 63) CP_WAIT(1); else CP_WAIT(0);   // V complete
        __syncthreads();

        // ---- l update + O rescale ----
#pragma unroll
        for (int hf = 0; hf < 2; hf++) {
            int lr = wm * 16 + g + 8 * hf;
            lreg[hf] = lreg[hf] * corr[hf] + reds[lr][0] + reds[lr][1];
#pragma unroll
            for (int nt = 0; nt < 8; nt++) {
                oacc[nt][hf * 2]     *= corr[hf];
                oacc[nt][hf * 2 + 1] *= corr[hf];
            }
        }

        // ---- O += P V ----
#pragma unroll
        for (int ks = 0; ks < 8; ks++) {
            uint32_t a[4], b[4][4];
            ldsm4(a, sb + PS_OFF + swz(wm * 16 + arow_l, 2 * ks + asel, 256));
#pragma unroll
            for (int pr = 0; pr < 4; pr++)
                ldsm4(b[pr], sb + VS_OFF + swz(wg * 64 + pr * 16 + brow_l,
                                               2 * ks + bsel, 256));
#pragma unroll
            for (int nt = 0; nt < 8; nt++)
                mma8(oacc[nt], a, &b[nt >> 1][(nt & 1) * 2]);
        }
    }

    // ---- finalize (round to tf32 for out-proj consumption) ----
    const int b = bh >> 3, h = bh & 7;
#pragma unroll
    for (int hf = 0; hf < 2; hf++) {
        float inv = 1.f / lreg[hf];
        int gi = i0 + wm * 16 + g + 8 * hf;
        size_t base = ((size_t)(b * NN + gi)) * 1024 + h * DH + wg * 64;
#pragma unroll
        for (int nt = 0; nt < 8; nt++)
            *(float2*)(g_att + base + nt * 8 + 2 * l4) =
                make_float2(rnd_tf32(oacc[nt][hf * 2] * inv),
                            rnd_tf32(oacc[nt][hf * 2 + 1] * inv));
    }
}

// ---------------- launcher ----------------
extern "C" void kernel_launch(void* const* d_in, const int* in_sizes, int n_in,
                              void* d_out, int out_size)
{
    const float* x     = (const float*)d_in[0];
    const float* W_qkv = (const float*)d_in[1];
    const float* W_out = (const float*)d_in[2];
    const float* b_out = (const float*)d_in[3];
    const int*   mask  = (const int*)  d_in[4];
    float* out = (float*)d_out;

    cudaFuncSetAttribute(attn_kernel,
                         cudaFuncAttributeMaxDynamicSharedMemorySize, ATT_SMEM);
    cudaFuncSetAttribute(mma_gemm<0>,
                         cudaFuncAttributeMaxDynamicSharedMemorySize, GEMM_SMEM);
    cudaFuncSetAttribute(mma_gemm<1>,
                         cudaFuncAttributeMaxDynamicSharedMemorySize, GEMM_SMEM);

    float* wqkvT; cudaGetSymbolAddress((void**)&wqkvT, g_wqkvT);
    float* woutT; cudaGetSymbolAddress((void**)&woutT, g_woutT);
    float* att;   cudaGetSymbolAddress((void**)&att, g_att);
    float* xr;    cudaGetSymbolAddress((void**)&xr, g_xr);

    round_x<<<8192, 256>>>(x, xr);
    transpose_k<<<dim3(96, 32), dim3(32, 8)>>>(W_qkv, wqkvT, 1024, 3072);
    transpose_k<<<dim3(32, 32), dim3(32, 8)>>>(W_out, woutT, 1024, 1024);

    mma_gemm<0><<<dim3(24, 64), 256, GEMM_SMEM>>>(xr, wqkvT, nullptr, nullptr);
    attn_kernel<<<dim3(32, 16), 512, ATT_SMEM>>>(mask);
    mma_gemm<1><<<dim3(8, 64), 256, GEMM_SMEM>>>(att, woutT, b_out, out);
}

// round 6
// speedup vs baseline: 1.0430x; 1.0430x over previous
#include <cuda_runtime.h>
#include <math.h>
#include <stdint.h>

#define NN 4096
#define HEADS 8
#define DH 128
#define MAXMASK 2048
#define ATT_SCALE 0.03125f  // 1024^-0.5

// ---------------- scratch ----------------
__device__ float g_xr [(size_t)8192*1024];   // x rounded to tf32
__device__ float g_q  [(size_t)16*NN*DH];    // [bh][n][d]
__device__ float g_k  [(size_t)16*NN*DH];    // [bh][n][d]
__device__ float g_vT [(size_t)16*DH*NN];    // [bh][d][n]
__device__ float g_att[(size_t)8192*1024];   // [b*n][dim]
__device__ float g_wqkvT[(size_t)3072*1024]; // W_qkv^T (tf32-rounded)
__device__ float g_woutT[(size_t)1024*1024]; // W_out^T (tf32-rounded)

// ---------------- helpers ----------------
__device__ __forceinline__ uint32_t smem_u32(const void* p) {
    uint32_t a;
    asm("{ .reg .u64 t; cvta.to.shared.u64 t, %1; cvt.u32.u64 %0, t; }"
        : "=r"(a) : "l"(p));
    return a;
}
__device__ __forceinline__ float rnd_tf32(float x) {
    uint32_t r;
    asm("cvt.rna.tf32.f32 %0, %1;" : "=r"(r) : "f"(x));
    return __uint_as_float(r);
}
__device__ __forceinline__ void cp16(uint32_t sdst, const void* gsrc) {
    asm volatile("cp.async.cg.shared.global [%0], [%1], 16;"
                 :: "r"(sdst), "l"(gsrc) : "memory");
}
#define CP_COMMIT() asm volatile("cp.async.commit_group;" ::: "memory")
#define CP_WAIT(n)  asm volatile("cp.async.wait_group %0;" :: "n"(n) : "memory")

__device__ __forceinline__ void ldsm4(uint32_t* r, uint32_t saddr) {
    asm volatile("ldmatrix.sync.aligned.m8n8.x4.shared.b16 {%0,%1,%2,%3}, [%4];"
        : "=r"(r[0]), "=r"(r[1]), "=r"(r[2]), "=r"(r[3]) : "r"(saddr));
}
__device__ __forceinline__ void mma8(float* d, const uint32_t* a, const uint32_t* b) {
    asm volatile(
        "mma.sync.aligned.m16n8k8.row.col.f32.tf32.tf32.f32 "
        "{%0,%1,%2,%3}, {%4,%5,%6,%7}, {%8,%9}, {%0,%1,%2,%3};"
        : "+f"(d[0]), "+f"(d[1]), "+f"(d[2]), "+f"(d[3])
        : "r"(a[0]), "r"(a[1]), "r"(a[2]), "r"(a[3]), "r"(b[0]), "r"(b[1]));
}
__device__ __forceinline__ uint32_t swz(int row, int slot, int rowb) {
    return (uint32_t)(row * rowb + ((slot ^ (row & 7)) << 4));
}

// ---------------- pre-round x to tf32 ----------------
__global__ void round_x(const float* __restrict__ in, float* __restrict__ outp)
{
    size_t i = ((size_t)blockIdx.x * blockDim.x + threadIdx.x) * 4;
    float4 v = *(const float4*)(in + i);
    v.x = rnd_tf32(v.x); v.y = rnd_tf32(v.y);
    v.z = rnd_tf32(v.z); v.w = rnd_tf32(v.w);
    *(float4*)(outp + i) = v;
}

// ---------------- weight transpose + tf32 round ----------------
__global__ void transpose_k(const float* __restrict__ in, float* __restrict__ outp,
                            int R, int C)
{
    __shared__ float t[32][33];
    int bx = blockIdx.x * 32, by = blockIdx.y * 32;
    int tx = threadIdx.x, ty = threadIdx.y;  // 32 x 8
#pragma unroll
    for (int i = 0; i < 32; i += 8)
        t[ty + i][tx] = in[(size_t)(by + ty + i) * C + bx + tx];
    __syncthreads();
#pragma unroll
    for (int i = 0; i < 32; i += 8)
        outp[(size_t)(bx + ty + i) * R + by + tx] = rnd_tf32(t[tx][ty + i]);
}

// ================= GEMM: C[M x Ncols] = A[M x 1024] * Bt[Ncols x 1024]^T =======
#define GEMM_SMEM 65536
template<int MODE>
__global__ __launch_bounds__(256, 2) void mma_gemm(
    const float* __restrict__ A, const float* __restrict__ Bt,
    const float* __restrict__ bias, float* __restrict__ out)
{
    extern __shared__ char sm[];
    const uint32_t sb = smem_u32(sm);
    const int tid = threadIdx.x, lane = tid & 31, wid = tid >> 5;
    const int wm = wid >> 2, wn = wid & 3;
    const int g = lane >> 2, l4 = lane & 3;
    const int m0 = blockIdx.y * 128, col0 = blockIdx.x * 128;

    const int arow_l = (lane & 7) + ((lane >> 3) & 1) * 8;
    const int asel = (lane >> 4) & 1;
    const int brow_l = (lane & 7) + ((lane >> 4) & 1) * 8;
    const int bsel = (lane >> 3) & 1;

    float acc[4][4][4];
#pragma unroll
    for (int mt = 0; mt < 4; mt++)
#pragma unroll
        for (int nt = 0; nt < 4; nt++)
#pragma unroll
            for (int r = 0; r < 4; r++) acc[mt][nt][r] = 0.f;

    auto fill = [&](int buf, int k0) {
#pragma unroll
        for (int i = 0; i < 4; i++) {
            int p = tid + i * 256;
            int r = p >> 3, s = p & 7;
            cp16(sb + buf * 16384 + swz(r, s, 128),
                 A + (size_t)(m0 + r) * 1024 + k0 + s * 4);
        }
#pragma unroll
        for (int i = 0; i < 4; i++) {
            int p = tid + i * 256;
            int r = p >> 3, s = p & 7;
            cp16(sb + 32768 + buf * 16384 + swz(r, s, 128),
                 Bt + (size_t)(col0 + r) * 1024 + k0 + s * 4);
        }
    };

    fill(0, 0);
    CP_COMMIT();

    for (int kb = 0; kb < 32; kb++) {
        CP_WAIT(0);
        __syncthreads();
        if (kb < 31) { fill((kb + 1) & 1, (kb + 1) * 32); CP_COMMIT(); }
        const uint32_t ab = sb + (kb & 1) * 16384;
        const uint32_t bb = sb + 32768 + (kb & 1) * 16384;
#pragma unroll
        for (int ks = 0; ks < 4; ks++) {
            uint32_t a[4][4], b[2][4];
#pragma unroll
            for (int mt = 0; mt < 4; mt++) {
                int row = wm * 64 + mt * 16 + arow_l;
                ldsm4(a[mt], ab + swz(row, 2 * ks + asel, 128));
            }
#pragma unroll
            for (int pr = 0; pr < 2; pr++) {
                int row = wn * 32 + pr * 16 + brow_l;
                ldsm4(b[pr], bb + swz(row, 2 * ks + bsel, 128));
            }
#pragma unroll
            for (int mt = 0; mt < 4; mt++)
#pragma unroll
                for (int nt = 0; nt < 4; nt++)
                    mma8(acc[mt][nt], a[mt], &b[nt >> 1][(nt & 1) * 2]);
        }
    }

    if (MODE == 0) {
        const int which = col0 >> 10;          // 0=q 1=k 2=v
        const int h = (col0 & 1023) >> 7;
#pragma unroll
        for (int mt = 0; mt < 4; mt++)
#pragma unroll
            for (int nt = 0; nt < 4; nt++) {
                int col = col0 + wn * 32 + nt * 8 + 2 * l4;
                int dd = col & 127;
#pragma unroll
                for (int hf = 0; hf < 2; hf++) {
                    int gr = m0 + wm * 64 + mt * 16 + g + 8 * hf;
                    int bb2 = gr >> 12, n = gr & 4095;
                    int bh = bb2 * HEADS + h;
                    float c0 = rnd_tf32(acc[mt][nt][hf * 2]);
                    float c1 = rnd_tf32(acc[mt][nt][hf * 2 + 1]);
                    if (which == 0)
                        *(float2*)(g_q + ((size_t)bh * NN + n) * DH + dd) = make_float2(c0, c1);
                    else if (which == 1)
                        *(float2*)(g_k + ((size_t)bh * NN + n) * DH + dd) = make_float2(c0, c1);
                    else {
                        float* dst = g_vT + ((size_t)bh * DH + dd) * NN + n;
                        dst[0] = c0; dst[NN] = c1;
                    }
                }
            }
    } else {
#pragma unroll
        for (int mt = 0; mt < 4; mt++)
#pragma unroll
            for (int nt = 0; nt < 4; nt++) {
                int col = col0 + wn * 32 + nt * 8 + 2 * l4;
                float2 bv = *(const float2*)(bias + col);
#pragma unroll
                for (int hf = 0; hf < 2; hf++) {
                    int gr = m0 + wm * 64 + mt * 16 + g + 8 * hf;
                    *(float2*)(out + (size_t)gr * 1024 + col) =
                        make_float2(acc[mt][nt][hf * 2] + bv.x,
                                    acc[mt][nt][hf * 2 + 1] + bv.y);
                }
            }
    }
}

// ================= Flash attention (256 threads, K+V double-buffered) ==========
// i-tile 128, j-tile 64. 8 warps: S role (wm 0..3, wg=wj 0..1) warp 32 rows x 32 j;
// PV role (wm, wg=wd) warp 32 rows x 64 d.
#define QS_OFF   0                        // 128 x 512B = 64KB
#define K_OFF(b) (65536 + (b) * 32768)    // 2 x 32KB
#define V_OFF(b) (131072 + (b) * 32768)   // 2 x 32KB (V^T: rows=d, cols=j)
#define PS_OFF   196608                   // 128 x 256B = 32KB
#define REDM_OFF 229376                   // float[128][2]
#define REDS_OFF 230400                   // float[128][2]
#define ATT_SMEM 231424

__global__ __launch_bounds__(256) void attn_kernel(const int* __restrict__ mask)
{
    extern __shared__ char sm[];
    const uint32_t sb = smem_u32(sm);
    float (*redm)[2] = (float(*)[2])(sm + REDM_OFF);
    float (*reds)[2] = (float(*)[2])(sm + REDS_OFF);

    const int tid = threadIdx.x, lane = tid & 31, wid = tid >> 5;
    const int wm = wid & 3, wg = wid >> 2;
    const int g = lane >> 2, l4 = lane & 3;
    const int i0 = blockIdx.x * 128;
    const int bh = blockIdx.y;

    const float* qP  = g_q  + (size_t)bh * NN * DH;
    const float* kP  = g_k  + (size_t)bh * NN * DH;
    const float* vTP = g_vT + (size_t)bh * DH * NN;

    const int arow_l = (lane & 7) + ((lane >> 3) & 1) * 8;
    const int asel = (lane >> 4) & 1;
    const int brow_l = (lane & 7) + ((lane >> 4) & 1) * 8;
    const int bsel = (lane >> 3) & 1;

    auto fillK = [&](int buf, int j0) {
#pragma unroll
        for (int i = 0; i < 8; i++) {
            int p = tid + i * 256;
            int r = p >> 5, s = p & 31;
            cp16(sb + K_OFF(buf) + swz(r, s, 512),
                 kP + (size_t)(j0 + r) * DH + s * 4);
        }
    };
    auto fillV = [&](int buf, int j0) {
#pragma unroll
        for (int i = 0; i < 8; i++) {
            int p = tid + i * 256;
            int r = p >> 4, s = p & 15;
            cp16(sb + V_OFF(buf) + swz(r, s, 256),
                 vTP + (size_t)r * NN + j0 + s * 4);
        }
    };

    // Q fill
#pragma unroll
    for (int i = 0; i < 16; i++) {
        int p = tid + i * 256;
        int r = p >> 5, s = p & 31;
        cp16(sb + QS_OFF + swz(r, s, 512), qP + (size_t)(i0 + r) * DH + s * 4);
    }
    fillK(0, 0);
    fillV(0, 0);
    CP_COMMIT();

    float oacc[2][8][4];
#pragma unroll
    for (int mt = 0; mt < 2; mt++)
#pragma unroll
        for (int nt = 0; nt < 8; nt++)
#pragma unroll
            for (int r = 0; r < 4; r++) oacc[mt][nt][r] = 0.f;
    float mreg[2][2] = {{-1e30f, -1e30f}, {-1e30f, -1e30f}};
    float lreg[2][2] = {{0.f, 0.f}, {0.f, 0.f}};

    for (int jt = 0; jt < 64; jt++) {
        const int j0 = jt * 64;
        CP_WAIT(0);          // K(jt), V(jt) landed
        __syncthreads();     // visible to all; prev iter P/V reads done

        // prefetch K/V for jt+1 (targets the buffers consumed in jt-1)
        if (jt < 63) {
            fillK((jt + 1) & 1, j0 + 64);
            fillV((jt + 1) & 1, j0 + 64);
            CP_COMMIT();
        }

        // ---- S = Q K^T ----
        float sacc[2][4][4];
#pragma unroll
        for (int mt = 0; mt < 2; mt++)
#pragma unroll
            for (int nt = 0; nt < 4; nt++)
#pragma unroll
                for (int r = 0; r < 4; r++) sacc[mt][nt][r] = 0.f;

        const uint32_t kb = sb + K_OFF(jt & 1);
#pragma unroll
        for (int ks = 0; ks < 16; ks++) {
            uint32_t a[2][4], b[2][4];
#pragma unroll
            for (int mt = 0; mt < 2; mt++) {
                int row = wm * 32 + mt * 16 + arow_l;
                ldsm4(a[mt], sb + QS_OFF + swz(row, 2 * ks + asel, 512));
            }
#pragma unroll
            for (int pr = 0; pr < 2; pr++) {
                int row = wg * 32 + pr * 16 + brow_l;
                ldsm4(b[pr], kb + swz(row, 2 * ks + bsel, 512));
            }
#pragma unroll
            for (int mt = 0; mt < 2; mt++)
#pragma unroll
                for (int nt = 0; nt < 4; nt++)
                    mma8(sacc[mt][nt], a[mt], &b[nt >> 1][(nt & 1) * 2]);
        }

        // ---- scale + mask ----
#pragma unroll
        for (int mt = 0; mt < 2; mt++)
#pragma unroll
            for (int nt = 0; nt < 4; nt++)
#pragma unroll
                for (int r = 0; r < 4; r++) sacc[mt][nt][r] *= ATT_SCALE;
        if (i0 < MAXMASK && j0 < MAXMASK) {
#pragma unroll
            for (int mt = 0; mt < 2; mt++)
#pragma unroll
                for (int hf = 0; hf < 2; hf++) {
                    int gi = i0 + wm * 32 + mt * 16 + g + 8 * hf;
                    const int* mp = mask + (size_t)gi * MAXMASK + j0 + wg * 32;
#pragma unroll
                    for (int nt = 0; nt < 4; nt++) {
                        int2 mv = *(const int2*)(mp + nt * 8 + 2 * l4);
                        if (mv.x == 0) sacc[mt][nt][hf * 2]     = -INFINITY;
                        if (mv.y == 0) sacc[mt][nt][hf * 2 + 1] = -INFINITY;
                    }
                }
        }

        // ---- softmax stage 1: per-row partial max ----
#pragma unroll
        for (int mt = 0; mt < 2; mt++)
#pragma unroll
            for (int hf = 0; hf < 2; hf++) {
                float pm = -INFINITY;
#pragma unroll
                for (int nt = 0; nt < 4; nt++)
                    pm = fmaxf(pm, fmaxf(sacc[mt][nt][hf * 2], sacc[mt][nt][hf * 2 + 1]));
                pm = fmaxf(pm, __shfl_xor_sync(0xffffffffu, pm, 1));
                pm = fmaxf(pm, __shfl_xor_sync(0xffffffffu, pm, 2));
                if (l4 == 0) redm[wm * 32 + mt * 16 + g + 8 * hf][wg] = pm;
            }
        __syncthreads();

        // ---- softmax stage 2: combine, exp, partial sums, P store ----
        float corr[2][2];
#pragma unroll
        for (int mt = 0; mt < 2; mt++)
#pragma unroll
            for (int hf = 0; hf < 2; hf++) {
                int lr = wm * 32 + mt * 16 + g + 8 * hf;
                float nm = fmaxf(fmaxf(redm[lr][0], redm[lr][1]), mreg[mt][hf]);
                float mc = fmaxf(nm, -1e30f);
                corr[mt][hf] = __expf(mreg[mt][hf] - mc);
                mreg[mt][hf] = mc;
                float rs = 0.f;
#pragma unroll
                for (int nt = 0; nt < 4; nt++) {
                    float p0 = __expf(sacc[mt][nt][hf * 2]     - mc);
                    float p1 = __expf(sacc[mt][nt][hf * 2 + 1] - mc);
                    rs += p0 + p1;
                    int cslot = wg * 8 + nt * 2 + (l4 >> 1);
                    *(float2*)(sm + PS_OFF + lr * 256
                               + ((cslot ^ (lr & 7)) << 4) + (l4 & 1) * 8) =
                        make_float2(rnd_tf32(p0), rnd_tf32(p1));
                }
                rs += __shfl_xor_sync(0xffffffffu, rs, 1);
                rs += __shfl_xor_sync(0xffffffffu, rs, 2);
                if (l4 == 0) reds[lr][wg] = rs;
            }
        __syncthreads();

        // ---- l update + O rescale ----
#pragma unroll
        for (int mt = 0; mt < 2; mt++)
#pragma unroll
            for (int hf = 0; hf < 2; hf++) {
                int lr = wm * 32 + mt * 16 + g + 8 * hf;
                lreg[mt][hf] = lreg[mt][hf] * corr[mt][hf] + reds[lr][0] + reds[lr][1];
#pragma unroll
                for (int nt = 0; nt < 8; nt++) {
                    oacc[mt][nt][hf * 2]     *= corr[mt][hf];
                    oacc[mt][nt][hf * 2 + 1] *= corr[mt][hf];
                }
            }

        // ---- O += P V ----
        const uint32_t vb = sb + V_OFF(jt & 1);
#pragma unroll
        for (int ks = 0; ks < 8; ks++) {
            uint32_t a[2][4], b[4][4];
#pragma unroll
            for (int mt = 0; mt < 2; mt++) {
                int row = wm * 32 + mt * 16 + arow_l;
                ldsm4(a[mt], sb + PS_OFF + swz(row, 2 * ks + asel, 256));
            }
#pragma unroll
            for (int pr = 0; pr < 4; pr++) {
                int row = wg * 64 + pr * 16 + brow_l;
                ldsm4(b[pr], vb + swz(row, 2 * ks + bsel, 256));
            }
#pragma unroll
            for (int mt = 0; mt < 2; mt++)
#pragma unroll
                for (int nt = 0; nt < 8; nt++)
                    mma8(oacc[mt][nt], a[mt], &b[nt >> 1][(nt & 1) * 2]);
        }
    }

    // ---- finalize (round to tf32 for out-proj consumption) ----
    const int b = bh >> 3, h = bh & 7;
#pragma unroll
    for (int mt = 0; mt < 2; mt++)
#pragma unroll
        for (int hf = 0; hf < 2; hf++) {
            float inv = 1.f / lreg[mt][hf];
            int gi = i0 + wm * 32 + mt * 16 + g + 8 * hf;
            size_t base = ((size_t)(b * NN + gi)) * 1024 + h * DH + wg * 64;
#pragma unroll
            for (int nt = 0; nt < 8; nt++)
                *(float2*)(g_att + base + nt * 8 + 2 * l4) =
                    make_float2(rnd_tf32(oacc[mt][nt][hf * 2] * inv),
                                rnd_tf32(oacc[mt][nt][hf * 2 + 1] * inv));
        }
}

// ---------------- launcher ----------------
extern "C" void kernel_launch(void* const* d_in, const int* in_sizes, int n_in,
                              void* d_out, int out_size)
{
    const float* x     = (const float*)d_in[0];
    const float* W_qkv = (const float*)d_in[1];
    const float* W_out = (const float*)d_in[2];
    const float* b_out = (const float*)d_in[3];
    const int*   mask  = (const int*)  d_in[4];
    float* out = (float*)d_out;

    cudaFuncSetAttribute(attn_kernel,
                         cudaFuncAttributeMaxDynamicSharedMemorySize, ATT_SMEM);
    cudaFuncSetAttribute(mma_gemm<0>,
                         cudaFuncAttributeMaxDynamicSharedMemorySize, GEMM_SMEM);
    cudaFuncSetAttribute(mma_gemm<1>,
                         cudaFuncAttributeMaxDynamicSharedMemorySize, GEMM_SMEM);

    float* wqkvT; cudaGetSymbolAddress((void**)&wqkvT, g_wqkvT);
    float* woutT; cudaGetSymbolAddress((void**)&woutT, g_woutT);
    float* att;   cudaGetSymbolAddress((void**)&att, g_att);
    float* xr;    cudaGetSymbolAddress((void**)&xr, g_xr);

    round_x<<<8192, 256>>>(x, xr);
    transpose_k<<<dim3(96, 32), dim3(32, 8)>>>(W_qkv, wqkvT, 1024, 3072);
    transpose_k<<<dim3(32, 32), dim3(32, 8)>>>(W_out, woutT, 1024, 1024);

    mma_gemm<0><<<dim3(24, 64), 256, GEMM_SMEM>>>(xr, wqkvT, nullptr, nullptr);
    attn_kernel<<<dim3(32, 16), 256, ATT_SMEM>>>(mask);
    mma_gemm<1><<<dim3(8, 64), 256, GEMM_SMEM>>>(att, woutT, b_out, out);
}

// round 7
// speedup vs baseline: 1.0861x; 1.0413x over previous
#include <cuda_runtime.h>
#include <math.h>
#include <stdint.h>

#define NN 4096
#define HEADS 8
#define DH 128
#define MAXMASK 2048
#define ATT_SCALE 0.03125f  // 1024^-0.5

// ---------------- scratch ----------------
__device__ float g_xr [(size_t)8192*1024];   // x rounded to tf32
__device__ float g_q  [(size_t)16*NN*DH];    // [bh][n][d]
__device__ float g_k  [(size_t)16*NN*DH];    // [bh][n][d]
__device__ float g_vT [(size_t)16*DH*NN];    // [bh][d][n]
__device__ float g_att[(size_t)8192*1024];   // [b*n][dim]
__device__ float g_wqkvT[(size_t)3072*1024]; // W_qkv^T (tf32-rounded)
__device__ float g_woutT[(size_t)1024*1024]; // W_out^T (tf32-rounded)

// ---------------- helpers ----------------
__device__ __forceinline__ uint32_t smem_u32(const void* p) {
    uint32_t a;
    asm("{ .reg .u64 t; cvta.to.shared.u64 t, %1; cvt.u32.u64 %0, t; }"
        : "=r"(a) : "l"(p));
    return a;
}
__device__ __forceinline__ float rnd_tf32(float x) {
    uint32_t r;
    asm("cvt.rna.tf32.f32 %0, %1;" : "=r"(r) : "f"(x));
    return __uint_as_float(r);
}
__device__ __forceinline__ void cp16(uint32_t sdst, const void* gsrc) {
    asm volatile("cp.async.cg.shared.global [%0], [%1], 16;"
                 :: "r"(sdst), "l"(gsrc) : "memory");
}
#define CP_COMMIT() asm volatile("cp.async.commit_group;" ::: "memory")
#define CP_WAIT(n)  asm volatile("cp.async.wait_group %0;" :: "n"(n) : "memory")

__device__ __forceinline__ void ldsm4(uint32_t* r, uint32_t saddr) {
    asm volatile("ldmatrix.sync.aligned.m8n8.x4.shared.b16 {%0,%1,%2,%3}, [%4];"
        : "=r"(r[0]), "=r"(r[1]), "=r"(r[2]), "=r"(r[3]) : "r"(saddr));
}
__device__ __forceinline__ void mma8(float* d, const uint32_t* a, const uint32_t* b) {
    asm volatile(
        "mma.sync.aligned.m16n8k8.row.col.f32.tf32.tf32.f32 "
        "{%0,%1,%2,%3}, {%4,%5,%6,%7}, {%8,%9}, {%0,%1,%2,%3};"
        : "+f"(d[0]), "+f"(d[1]), "+f"(d[2]), "+f"(d[3])
        : "r"(a[0]), "r"(a[1]), "r"(a[2]), "r"(a[3]), "r"(b[0]), "r"(b[1]));
}
__device__ __forceinline__ uint32_t swz(int row, int slot, int rowb) {
    return (uint32_t)(row * rowb + ((slot ^ (row & 7)) << 4));
}

// ---------------- pre-round x to tf32 ----------------
__global__ void round_x(const float* __restrict__ in, float* __restrict__ outp)
{
    size_t i = ((size_t)blockIdx.x * blockDim.x + threadIdx.x) * 4;
    float4 v = *(const float4*)(in + i);
    v.x = rnd_tf32(v.x); v.y = rnd_tf32(v.y);
    v.z = rnd_tf32(v.z); v.w = rnd_tf32(v.w);
    *(float4*)(outp + i) = v;
}

// ---------------- weight transpose + tf32 round ----------------
__global__ void transpose_k(const float* __restrict__ in, float* __restrict__ outp,
                            int R, int C)
{
    __shared__ float t[32][33];
    int bx = blockIdx.x * 32, by = blockIdx.y * 32;
    int tx = threadIdx.x, ty = threadIdx.y;  // 32 x 8
#pragma unroll
    for (int i = 0; i < 32; i += 8)
        t[ty + i][tx] = in[(size_t)(by + ty + i) * C + bx + tx];
    __syncthreads();
#pragma unroll
    for (int i = 0; i < 32; i += 8)
        outp[(size_t)(bx + ty + i) * R + by + tx] = rnd_tf32(t[tx][ty + i]);
}

// ================= GEMM: C[M x Ncols] = A[M x 1024] * Bt[Ncols x 1024]^T =======
#define GEMM_SMEM 65536
template<int MODE>
__global__ __launch_bounds__(256, 2) void mma_gemm(
    const float* __restrict__ A, const float* __restrict__ Bt,
    const float* __restrict__ bias, float* __restrict__ out)
{
    extern __shared__ char sm[];
    const uint32_t sb = smem_u32(sm);
    const int tid = threadIdx.x, lane = tid & 31, wid = tid >> 5;
    const int wm = wid >> 2, wn = wid & 3;
    const int g = lane >> 2, l4 = lane & 3;
    const int m0 = blockIdx.y * 128, col0 = blockIdx.x * 128;

    const int arow_l = (lane & 7) + ((lane >> 3) & 1) * 8;
    const int asel = (lane >> 4) & 1;
    const int brow_l = (lane & 7) + ((lane >> 4) & 1) * 8;
    const int bsel = (lane >> 3) & 1;

    float acc[4][4][4];
#pragma unroll
    for (int mt = 0; mt < 4; mt++)
#pragma unroll
        for (int nt = 0; nt < 4; nt++)
#pragma unroll
            for (int r = 0; r < 4; r++) acc[mt][nt][r] = 0.f;

    auto fill = [&](int buf, int k0) {
#pragma unroll
        for (int i = 0; i < 4; i++) {
            int p = tid + i * 256;
            int r = p >> 3, s = p & 7;
            cp16(sb + buf * 16384 + swz(r, s, 128),
                 A + (size_t)(m0 + r) * 1024 + k0 + s * 4);
        }
#pragma unroll
        for (int i = 0; i < 4; i++) {
            int p = tid + i * 256;
            int r = p >> 3, s = p & 7;
            cp16(sb + 32768 + buf * 16384 + swz(r, s, 128),
                 Bt + (size_t)(col0 + r) * 1024 + k0 + s * 4);
        }
    };

    fill(0, 0);
    CP_COMMIT();

    for (int kb = 0; kb < 32; kb++) {
        CP_WAIT(0);
        __syncthreads();
        if (kb < 31) { fill((kb + 1) & 1, (kb + 1) * 32); CP_COMMIT(); }
        const uint32_t ab = sb + (kb & 1) * 16384;
        const uint32_t bb = sb + 32768 + (kb & 1) * 16384;
#pragma unroll
        for (int ks = 0; ks < 4; ks++) {
            uint32_t a[4][4], b[2][4];
#pragma unroll
            for (int mt = 0; mt < 4; mt++) {
                int row = wm * 64 + mt * 16 + arow_l;
                ldsm4(a[mt], ab + swz(row, 2 * ks + asel, 128));
            }
#pragma unroll
            for (int pr = 0; pr < 2; pr++) {
                int row = wn * 32 + pr * 16 + brow_l;
                ldsm4(b[pr], bb + swz(row, 2 * ks + bsel, 128));
            }
#pragma unroll
            for (int mt = 0; mt < 4; mt++)
#pragma unroll
                for (int nt = 0; nt < 4; nt++)
                    mma8(acc[mt][nt], a[mt], &b[nt >> 1][(nt & 1) * 2]);
        }
    }

    if (MODE == 0) {
        const int which = col0 >> 10;          // 0=q 1=k 2=v
        const int h = (col0 & 1023) >> 7;
#pragma unroll
        for (int mt = 0; mt < 4; mt++)
#pragma unroll
            for (int nt = 0; nt < 4; nt++) {
                int col = col0 + wn * 32 + nt * 8 + 2 * l4;
                int dd = col & 127;
#pragma unroll
                for (int hf = 0; hf < 2; hf++) {
                    int gr = m0 + wm * 64 + mt * 16 + g + 8 * hf;
                    int bb2 = gr >> 12, n = gr & 4095;
                    int bh = bb2 * HEADS + h;
                    float c0 = rnd_tf32(acc[mt][nt][hf * 2]);
                    float c1 = rnd_tf32(acc[mt][nt][hf * 2 + 1]);
                    if (which == 0)
                        *(float2*)(g_q + ((size_t)bh * NN + n) * DH + dd) = make_float2(c0, c1);
                    else if (which == 1)
                        *(float2*)(g_k + ((size_t)bh * NN + n) * DH + dd) = make_float2(c0, c1);
                    else {
                        float* dst = g_vT + ((size_t)bh * DH + dd) * NN + n;
                        dst[0] = c0; dst[NN] = c1;
                    }
                }
            }
    } else {
#pragma unroll
        for (int mt = 0; mt < 4; mt++)
#pragma unroll
            for (int nt = 0; nt < 4; nt++) {
                int col = col0 + wn * 32 + nt * 8 + 2 * l4;
                float2 bv = *(const float2*)(bias + col);
#pragma unroll
                for (int hf = 0; hf < 2; hf++) {
                    int gr = m0 + wm * 64 + mt * 16 + g + 8 * hf;
                    *(float2*)(out + (size_t)gr * 1024 + col) =
                        make_float2(acc[mt][nt][hf * 2] + bv.x,
                                    acc[mt][nt][hf * 2 + 1] + bv.y);
                }
            }
    }
}

// ================= Flash attention v3: rows-per-warp, 1 barrier/jt ============
// i-tile 128, j-tile 64, 8 warps. Warp w owns rows 16w..16w+15 for BOTH S and PV.
// S: 16x64 (k=128); PV: 16x128 (k=64). Softmax: registers + quad shuffles only.
// P is warp-private in smem (own 16 rows) -> __syncwarp, not __syncthreads.
#define QS_OFF   0                        // 128 x 512B = 64KB
#define K_OFF(b) (65536 + (b) * 32768)    // 2 x 32KB (64 rows x 512B)
#define V_OFF(b) (131072 + (b) * 32768)   // 2 x 32KB (V^T: 128 d-rows x 256B)
#define PS_OFF   196608                   // 128 x 256B = 32KB
#define ATT_SMEM 229376

__global__ __launch_bounds__(256) void attn_kernel(const int* __restrict__ mask)
{
    extern __shared__ char sm[];
    const uint32_t sb = smem_u32(sm);

    const int tid = threadIdx.x, lane = tid & 31, wid = tid >> 5;
    const int g = lane >> 2, l4 = lane & 3;
    const int i0 = blockIdx.x * 128;
    const int bh = blockIdx.y;

    const float* qP  = g_q  + (size_t)bh * NN * DH;
    const float* kP  = g_k  + (size_t)bh * NN * DH;
    const float* vTP = g_vT + (size_t)bh * DH * NN;

    const int arow_l = (lane & 7) + ((lane >> 3) & 1) * 8;
    const int asel = (lane >> 4) & 1;
    const int brow_l = (lane & 7) + ((lane >> 4) & 1) * 8;
    const int bsel = (lane >> 3) & 1;

    auto fillK = [&](int buf, int j0) {
#pragma unroll
        for (int i = 0; i < 8; i++) {
            int p = tid + i * 256;
            int r = p >> 5, s = p & 31;
            cp16(sb + K_OFF(buf) + swz(r, s, 512),
                 kP + (size_t)(j0 + r) * DH + s * 4);
        }
    };
    auto fillV = [&](int buf, int j0) {
#pragma unroll
        for (int i = 0; i < 8; i++) {
            int p = tid + i * 256;
            int r = p >> 4, s = p & 15;
            cp16(sb + V_OFF(buf) + swz(r, s, 256),
                 vTP + (size_t)r * NN + j0 + s * 4);
        }
    };

    // Q fill
#pragma unroll
    for (int i = 0; i < 16; i++) {
        int p = tid + i * 256;
        int r = p >> 5, s = p & 31;
        cp16(sb + QS_OFF + swz(r, s, 512), qP + (size_t)(i0 + r) * DH + s * 4);
    }
    fillK(0, 0);
    fillV(0, 0);
    CP_COMMIT();

    float oacc[16][4];
#pragma unroll
    for (int nt = 0; nt < 16; nt++)
#pragma unroll
        for (int r = 0; r < 4; r++) oacc[nt][r] = 0.f;
    float mreg[2] = {-1e30f, -1e30f};
    float lreg[2] = {0.f, 0.f};

    for (int jt = 0; jt < 64; jt++) {
        const int j0 = jt * 64;
        CP_WAIT(0);          // K(jt), V(jt) landed
        __syncthreads();     // all warps done reading prev buffers

        if (jt < 63) {       // prefetch next (opposite buffers; issued post-barrier)
            fillK((jt + 1) & 1, j0 + 64);
            fillV((jt + 1) & 1, j0 + 64);
            CP_COMMIT();
        }

        // ---- S = Q K^T : warp = 16 rows x 64 j, k=128 ----
        float sacc[8][4];
#pragma unroll
        for (int nt = 0; nt < 8; nt++)
#pragma unroll
            for (int r = 0; r < 4; r++) sacc[nt][r] = 0.f;

        const uint32_t kb = sb + K_OFF(jt & 1);
#pragma unroll
        for (int ks = 0; ks < 16; ks++) {
            uint32_t a[4], b[4][4];
            ldsm4(a, sb + QS_OFF + swz(wid * 16 + arow_l, 2 * ks + asel, 512));
#pragma unroll
            for (int pr = 0; pr < 4; pr++)
                ldsm4(b[pr], kb + swz(pr * 16 + brow_l, 2 * ks + bsel, 512));
#pragma unroll
            for (int nt = 0; nt < 8; nt++)
                mma8(sacc[nt], a, &b[nt >> 1][(nt & 1) * 2]);
        }

        // ---- scale + mask ----
#pragma unroll
        for (int nt = 0; nt < 8; nt++)
#pragma unroll
            for (int r = 0; r < 4; r++) sacc[nt][r] *= ATT_SCALE;
        if (i0 < MAXMASK && j0 < MAXMASK) {
#pragma unroll
            for (int hf = 0; hf < 2; hf++) {
                int gi = i0 + wid * 16 + g + 8 * hf;
                const int* mp = mask + (size_t)gi * MAXMASK + j0;
#pragma unroll
                for (int nt = 0; nt < 8; nt++) {
                    int2 mv = *(const int2*)(mp + nt * 8 + 2 * l4);
                    if (mv.x == 0) sacc[nt][hf * 2]     = -INFINITY;
                    if (mv.y == 0) sacc[nt][hf * 2 + 1] = -INFINITY;
                }
            }
        }

        // ---- softmax: fully in-warp (quad shuffles) ----
#pragma unroll
        for (int hf = 0; hf < 2; hf++) {
            int lr = wid * 16 + g + 8 * hf;
            float pm = -INFINITY;
#pragma unroll
            for (int nt = 0; nt < 8; nt++)
                pm = fmaxf(pm, fmaxf(sacc[nt][hf * 2], sacc[nt][hf * 2 + 1]));
            pm = fmaxf(pm, __shfl_xor_sync(0xffffffffu, pm, 1));
            pm = fmaxf(pm, __shfl_xor_sync(0xffffffffu, pm, 2));
            float mc = fmaxf(fmaxf(mreg[hf], pm), -1e30f);
            float corr = __expf(mreg[hf] - mc);
            mreg[hf] = mc;
            float rs = 0.f;
#pragma unroll
            for (int nt = 0; nt < 8; nt++) {
                float p0 = __expf(sacc[nt][hf * 2]     - mc);
                float p1 = __expf(sacc[nt][hf * 2 + 1] - mc);
                rs += p0 + p1;
                int cslot = nt * 2 + (l4 >> 1);
                *(float2*)(sm + PS_OFF + lr * 256
                           + ((cslot ^ (lr & 7)) << 4) + (l4 & 1) * 8) =
                    make_float2(rnd_tf32(p0), rnd_tf32(p1));
            }
            rs += __shfl_xor_sync(0xffffffffu, rs, 1);
            rs += __shfl_xor_sync(0xffffffffu, rs, 2);
            lreg[hf] = lreg[hf] * corr + rs;
#pragma unroll
            for (int nt = 0; nt < 16; nt++) {
                oacc[nt][hf * 2]     *= corr;
                oacc[nt][hf * 2 + 1] *= corr;
            }
        }
        __syncwarp();   // P rows are warp-private: order STS before LDSM

        // ---- O += P V : warp = 16 rows x 128 d, k=64 ----
        const uint32_t vb = sb + V_OFF(jt & 1);
#pragma unroll
        for (int ks = 0; ks < 8; ks++) {
            uint32_t a[4], b[8][4];
            ldsm4(a, sb + PS_OFF + swz(wid * 16 + arow_l, 2 * ks + asel, 256));
#pragma unroll
            for (int pr = 0; pr < 8; pr++)
                ldsm4(b[pr], vb + swz(pr * 16 + brow_l, 2 * ks + bsel, 256));
#pragma unroll
            for (int nt = 0; nt < 16; nt++)
                mma8(oacc[nt], a, &b[nt >> 1][(nt & 1) * 2]);
        }
    }

    // ---- finalize (round to tf32 for out-proj consumption) ----
    const int b = bh >> 3, h = bh & 7;
#pragma unroll
    for (int hf = 0; hf < 2; hf++) {
        float inv = 1.f / lreg[hf];
        int gi = i0 + wid * 16 + g + 8 * hf;
        size_t base = ((size_t)(b * NN + gi)) * 1024 + h * DH;
#pragma unroll
        for (int nt = 0; nt < 16; nt++)
            *(float2*)(g_att + base + nt * 8 + 2 * l4) =
                make_float2(rnd_tf32(oacc[nt][hf * 2] * inv),
                            rnd_tf32(oacc[nt][hf * 2 + 1] * inv));
    }
}

// ---------------- launcher ----------------
extern "C" void kernel_launch(void* const* d_in, const int* in_sizes, int n_in,
                              void* d_out, int out_size)
{
    const float* x     = (const float*)d_in[0];
    const float* W_qkv = (const float*)d_in[1];
    const float* W_out = (const float*)d_in[2];
    const float* b_out = (const float*)d_in[3];
    const int*   mask  = (const int*)  d_in[4];
    float* out = (float*)d_out;

    cudaFuncSetAttribute(attn_kernel,
                         cudaFuncAttributeMaxDynamicSharedMemorySize, ATT_SMEM);
    cudaFuncSetAttribute(mma_gemm<0>,
                         cudaFuncAttributeMaxDynamicSharedMemorySize, GEMM_SMEM);
    cudaFuncSetAttribute(mma_gemm<1>,
                         cudaFuncAttributeMaxDynamicSharedMemorySize, GEMM_SMEM);

    float* wqkvT; cudaGetSymbolAddress((void**)&wqkvT, g_wqkvT);
    float* woutT; cudaGetSymbolAddress((void**)&woutT, g_woutT);
    float* att;   cudaGetSymbolAddress((void**)&att, g_att);
    float* xr;    cudaGetSymbolAddress((void**)&xr, g_xr);

    round_x<<<8192, 256>>>(x, xr);
    transpose_k<<<dim3(96, 32), dim3(32, 8)>>>(W_qkv, wqkvT, 1024, 3072);
    transpose_k<<<dim3(32, 32), dim3(32, 8)>>>(W_out, woutT, 1024, 1024);

    mma_gemm<0><<<dim3(24, 64), 256, GEMM_SMEM>>>(xr, wqkvT, nullptr, nullptr);
    attn_kernel<<<dim3(32, 16), 256, ATT_SMEM>>>(mask);
    mma_gemm<1><<<dim3(8, 64), 256, GEMM_SMEM>>>(att, woutT, b_out, out);
}

// round 8
// speedup vs baseline: 1.8325x; 1.6871x over previous
#include <cuda_runtime.h>
#include <cuda_fp16.h>
#include <math.h>
#include <stdint.h>

#define NN 4096
#define HEADS 8
#define DH 128
#define MAXMASK 2048
#define ATT_SCALE 0.03125f  // 1024^-0.5

// ---------------- scratch (fp16 operands everywhere) ----------------
__device__ __half g_xh [(size_t)8192*1024];   // x in fp16
__device__ __half g_q  [(size_t)16*NN*DH];    // [bh][n][d]
__device__ __half g_k  [(size_t)16*NN*DH];    // [bh][n][d]
__device__ __half g_vT [(size_t)16*DH*NN];    // [bh][d][n]
__device__ __half g_att[(size_t)8192*1024];   // [b*n][dim]
__device__ __half g_wqkvT[(size_t)3072*1024]; // W_qkv^T fp16
__device__ __half g_woutT[(size_t)1024*1024]; // W_out^T fp16

// ---------------- helpers ----------------
__device__ __forceinline__ uint32_t smem_u32(const void* p) {
    uint32_t a;
    asm("{ .reg .u64 t; cvta.to.shared.u64 t, %1; cvt.u32.u64 %0, t; }"
        : "=r"(a) : "l"(p));
    return a;
}
__device__ __forceinline__ void cp16(uint32_t sdst, const void* gsrc) {
    asm volatile("cp.async.cg.shared.global [%0], [%1], 16;"
                 :: "r"(sdst), "l"(gsrc) : "memory");
}
#define CP_COMMIT() asm volatile("cp.async.commit_group;" ::: "memory")
#define CP_WAIT(n)  asm volatile("cp.async.wait_group %0;" :: "n"(n) : "memory")

__device__ __forceinline__ void ldsm4(uint32_t* r, uint32_t saddr) {
    asm volatile("ldmatrix.sync.aligned.m8n8.x4.shared.b16 {%0,%1,%2,%3}, [%4];"
        : "=r"(r[0]), "=r"(r[1]), "=r"(r[2]), "=r"(r[3]) : "r"(saddr));
}
// fp16 MMA, fp32 accumulate: D[16x8] += A[16x16] B[16x8]
__device__ __forceinline__ void mma16(float* d, const uint32_t* a, const uint32_t* b) {
    asm volatile(
        "mma.sync.aligned.m16n8k16.row.col.f32.f16.f16.f32 "
        "{%0,%1,%2,%3}, {%4,%5,%6,%7}, {%8,%9}, {%0,%1,%2,%3};"
        : "+f"(d[0]), "+f"(d[1]), "+f"(d[2]), "+f"(d[3])
        : "r"(a[0]), "r"(a[1]), "r"(a[2]), "r"(a[3]), "r"(b[0]), "r"(b[1]));
}
__device__ __forceinline__ uint32_t swz(int row, int slot, int rowb) {
    return (uint32_t)(row * rowb + ((slot ^ (row & 7)) << 4));
}
__device__ __forceinline__ uint32_t packh2(float a, float b) {
    __half2 h = __floats2half2_rn(a, b);
    return *(uint32_t*)&h;
}

// ---------------- convert x to fp16 ----------------
__global__ void conv_x(const float* __restrict__ in, __half* __restrict__ outp)
{
    size_t i = ((size_t)blockIdx.x * blockDim.x + threadIdx.x) * 8;
    float4 v0 = *(const float4*)(in + i);
    float4 v1 = *(const float4*)(in + i + 4);
    uint4 o;
    o.x = packh2(v0.x, v0.y); o.y = packh2(v0.z, v0.w);
    o.z = packh2(v1.x, v1.y); o.w = packh2(v1.z, v1.w);
    *(uint4*)(outp + i) = o;
}

// ---------------- weight transpose + fp16 convert: in[R][C] -> out[C][R] ------
__global__ void transpose_k(const float* __restrict__ in, __half* __restrict__ outp,
                            int R, int C)
{
    __shared__ float t[32][33];
    int bx = blockIdx.x * 32, by = blockIdx.y * 32;
    int tx = threadIdx.x, ty = threadIdx.y;  // 32 x 8
#pragma unroll
    for (int i = 0; i < 32; i += 8)
        t[ty + i][tx] = in[(size_t)(by + ty + i) * C + bx + tx];
    __syncthreads();
#pragma unroll
    for (int i = 0; i < 32; i += 8)
        outp[(size_t)(bx + ty + i) * R + by + tx] = __float2half(t[tx][ty + i]);
}

// ================= fp16 GEMM: C[M x Ncols] = A[M x 1024] * Bt[Ncols x 1024]^T ==
// CTA 128x128, BK=64 fp16 (128B rows), double-buffered, warps 2m x 4n (64x32).
#define GEMM_SMEM 65536
template<int MODE>
__global__ __launch_bounds__(256, 2) void mma_gemm(
    const __half* __restrict__ A, const __half* __restrict__ Bt,
    const float* __restrict__ bias, float* __restrict__ out)
{
    extern __shared__ char sm[];
    const uint32_t sb = smem_u32(sm);
    const int tid = threadIdx.x, lane = tid & 31, wid = tid >> 5;
    const int wm = wid >> 2, wn = wid & 3;
    const int g = lane >> 2, l4 = lane & 3;
    const int m0 = blockIdx.y * 128, col0 = blockIdx.x * 128;

    const int arow_l = lane & 15;
    const int asel = (lane >> 4) & 1;
    const int brow_l = (lane & 7) + ((lane >> 4) & 1) * 8;
    const int bsel = (lane >> 3) & 1;

    float acc[4][4][4];
#pragma unroll
    for (int mt = 0; mt < 4; mt++)
#pragma unroll
        for (int nt = 0; nt < 4; nt++)
#pragma unroll
            for (int r = 0; r < 4; r++) acc[mt][nt][r] = 0.f;

    auto fill = [&](int buf, int k0) {
#pragma unroll
        for (int i = 0; i < 2; i++) {
            int p = tid + i * 256;
            int r = p >> 2, s = (p & 3) * 2;      // 128 rows x 8 slots, 2 slots/thread
            cp16(sb + buf * 16384 + swz(r, s, 128),
                 A + (size_t)(m0 + r) * 1024 + k0 + s * 8);
            cp16(sb + buf * 16384 + swz(r, s + 1, 128),
                 A + (size_t)(m0 + r) * 1024 + k0 + s * 8 + 8);
        }
#pragma unroll
        for (int i = 0; i < 2; i++) {
            int p = tid + i * 256;
            int r = p >> 2, s = (p & 3) * 2;
            cp16(sb + 32768 + buf * 16384 + swz(r, s, 128),
                 Bt + (size_t)(col0 + r) * 1024 + k0 + s * 8);
            cp16(sb + 32768 + buf * 16384 + swz(r, s + 1, 128),
                 Bt + (size_t)(col0 + r) * 1024 + k0 + s * 8 + 8);
        }
    };

    fill(0, 0);
    CP_COMMIT();

    for (int kb = 0; kb < 16; kb++) {
        CP_WAIT(0);
        __syncthreads();
        if (kb < 15) { fill((kb + 1) & 1, (kb + 1) * 64); CP_COMMIT(); }
        const uint32_t ab = sb + (kb & 1) * 16384;
        const uint32_t bb = sb + 32768 + (kb & 1) * 16384;
#pragma unroll
        for (int ks = 0; ks < 4; ks++) {          // 4 x k16
            uint32_t a[4][4], b[2][4];
#pragma unroll
            for (int mt = 0; mt < 4; mt++) {
                int row = wm * 64 + mt * 16 + arow_l;
                ldsm4(a[mt], ab + swz(row, 2 * ks + asel, 128));
            }
#pragma unroll
            for (int pr = 0; pr < 2; pr++) {
                int row = wn * 32 + pr * 16 + brow_l;
                ldsm4(b[pr], bb + swz(row, 2 * ks + bsel, 128));
            }
#pragma unroll
            for (int mt = 0; mt < 4; mt++)
#pragma unroll
                for (int nt = 0; nt < 4; nt++)
                    mma16(acc[mt][nt], a[mt], &b[nt >> 1][(nt & 1) * 2]);
        }
    }

    if (MODE == 0) {
        const int which = col0 >> 10;          // 0=q 1=k 2=v
        const int h = (col0 & 1023) >> 7;
#pragma unroll
        for (int mt = 0; mt < 4; mt++)
#pragma unroll
            for (int nt = 0; nt < 4; nt++) {
                int col = col0 + wn * 32 + nt * 8 + 2 * l4;
                int dd = col & 127;
#pragma unroll
                for (int hf = 0; hf < 2; hf++) {
                    int gr = m0 + wm * 64 + mt * 16 + g + 8 * hf;
                    int bb2 = gr >> 12, n = gr & 4095;
                    int bh = bb2 * HEADS + h;
                    float c0 = acc[mt][nt][hf * 2], c1 = acc[mt][nt][hf * 2 + 1];
                    if (which == 0)
                        *(uint32_t*)(g_q + ((size_t)bh * NN + n) * DH + dd) = packh2(c0, c1);
                    else if (which == 1)
                        *(uint32_t*)(g_k + ((size_t)bh * NN + n) * DH + dd) = packh2(c0, c1);
                    else {
                        __half* dst = g_vT + ((size_t)bh * DH + dd) * NN + n;
                        dst[0] = __float2half(c0); dst[NN] = __float2half(c1);
                    }
                }
            }
    } else {
#pragma unroll
        for (int mt = 0; mt < 4; mt++)
#pragma unroll
            for (int nt = 0; nt < 4; nt++) {
                int col = col0 + wn * 32 + nt * 8 + 2 * l4;
                float2 bv = *(const float2*)(bias + col);
#pragma unroll
                for (int hf = 0; hf < 2; hf++) {
                    int gr = m0 + wm * 64 + mt * 16 + g + 8 * hf;
                    *(float2*)(out + (size_t)gr * 1024 + col) =
                        make_float2(acc[mt][nt][hf * 2] + bv.x,
                                    acc[mt][nt][hf * 2 + 1] + bv.y);
                }
            }
    }
}

// ================= Flash attention fp16 (rows-per-warp, 1 barrier/jt) =========
// i-tile 128, j-tile 64, 8 warps; warp w owns rows 16w..16w+15 for S and PV.
// Q: 128 x 256B = 32KB; K: 2 x (64 x 256B) = 32KB; V^T: 2 x (128 x 128B) = 32KB;
// P: 128 x 128B = 16KB.  Total 112KB.
#define QS_OFF   0
#define K_OFF(b) (32768 + (b) * 16384)
#define V_OFF(b) (65536 + (b) * 16384)
#define PS_OFF   98304
#define ATT_SMEM 114688

__global__ __launch_bounds__(256) void attn_kernel(const int* __restrict__ mask)
{
    extern __shared__ char sm[];
    const uint32_t sb = smem_u32(sm);

    const int tid = threadIdx.x, lane = tid & 31, wid = tid >> 5;
    const int g = lane >> 2, l4 = lane & 3;
    const int i0 = blockIdx.x * 128;
    const int bh = blockIdx.y;

    const __half* qP  = g_q  + (size_t)bh * NN * DH;
    const __half* kP  = g_k  + (size_t)bh * NN * DH;
    const __half* vTP = g_vT + (size_t)bh * DH * NN;

    const int arow_l = lane & 15;
    const int asel = (lane >> 4) & 1;
    const int brow_l = (lane & 7) + ((lane >> 4) & 1) * 8;
    const int bsel = (lane >> 3) & 1;

    auto fillK = [&](int buf, int j0) {           // 64 rows x 16 slots
#pragma unroll
        for (int i = 0; i < 4; i++) {
            int p = tid + i * 256;
            int r = p >> 4, s = p & 15;
            cp16(sb + K_OFF(buf) + swz(r, s, 256),
                 kP + (size_t)(j0 + r) * DH + s * 8);
        }
    };
    auto fillV = [&](int buf, int j0) {           // 128 d-rows x 8 slots
#pragma unroll
        for (int i = 0; i < 4; i++) {
            int p = tid + i * 256;
            int r = p >> 3, s = p & 7;
            cp16(sb + V_OFF(buf) + swz(r, s, 128),
                 vTP + (size_t)r * NN + j0 + s * 8);
        }
    };

    // Q fill: 128 rows x 16 slots
#pragma unroll
    for (int i = 0; i < 8; i++) {
        int p = tid + i * 256;
        int r = p >> 4, s = p & 15;
        cp16(sb + QS_OFF + swz(r, s, 256), qP + (size_t)(i0 + r) * DH + s * 8);
    }
    fillK(0, 0);
    fillV(0, 0);
    CP_COMMIT();

    float oacc[16][4];
#pragma unroll
    for (int nt = 0; nt < 16; nt++)
#pragma unroll
        for (int r = 0; r < 4; r++) oacc[nt][r] = 0.f;
    float mreg[2] = {-1e30f, -1e30f};
    float lreg[2] = {0.f, 0.f};

    for (int jt = 0; jt < 64; jt++) {
        const int j0 = jt * 64;
        CP_WAIT(0);
        __syncthreads();

        if (jt < 63) {
            fillK((jt + 1) & 1, j0 + 64);
            fillV((jt + 1) & 1, j0 + 64);
            CP_COMMIT();
        }

        // ---- S = Q K^T : 16 rows x 64 j, k=128 (8 x k16) ----
        float sacc[8][4];
#pragma unroll
        for (int nt = 0; nt < 8; nt++)
#pragma unroll
            for (int r = 0; r < 4; r++) sacc[nt][r] = 0.f;

        const uint32_t kb = sb + K_OFF(jt & 1);
#pragma unroll
        for (int ks = 0; ks < 8; ks++) {
            uint32_t a[4], b[4][4];
            ldsm4(a, sb + QS_OFF + swz(wid * 16 + arow_l, 2 * ks + asel, 256));
#pragma unroll
            for (int pr = 0; pr < 4; pr++)
                ldsm4(b[pr], kb + swz(pr * 16 + brow_l, 2 * ks + bsel, 256));
#pragma unroll
            for (int nt = 0; nt < 8; nt++)
                mma16(sacc[nt], a, &b[nt >> 1][(nt & 1) * 2]);
        }

        // ---- scale + mask ----
#pragma unroll
        for (int nt = 0; nt < 8; nt++)
#pragma unroll
            for (int r = 0; r < 4; r++) sacc[nt][r] *= ATT_SCALE;
        if (i0 < MAXMASK && j0 < MAXMASK) {
#pragma unroll
            for (int hf = 0; hf < 2; hf++) {
                int gi = i0 + wid * 16 + g + 8 * hf;
                const int* mp = mask + (size_t)gi * MAXMASK + j0;
#pragma unroll
                for (int nt = 0; nt < 8; nt++) {
                    int2 mv = *(const int2*)(mp + nt * 8 + 2 * l4);
                    if (mv.x == 0) sacc[nt][hf * 2]     = -INFINITY;
                    if (mv.y == 0) sacc[nt][hf * 2 + 1] = -INFINITY;
                }
            }
        }

        // ---- softmax: fully in-warp ----
#pragma unroll
        for (int hf = 0; hf < 2; hf++) {
            int lr = wid * 16 + g + 8 * hf;
            float pm = -INFINITY;
#pragma unroll
            for (int nt = 0; nt < 8; nt++)
                pm = fmaxf(pm, fmaxf(sacc[nt][hf * 2], sacc[nt][hf * 2 + 1]));
            pm = fmaxf(pm, __shfl_xor_sync(0xffffffffu, pm, 1));
            pm = fmaxf(pm, __shfl_xor_sync(0xffffffffu, pm, 2));
            float mc = fmaxf(fmaxf(mreg[hf], pm), -1e30f);
            float corr = __expf(mreg[hf] - mc);
            mreg[hf] = mc;
            float rs = 0.f;
#pragma unroll
            for (int nt = 0; nt < 8; nt++) {
                float p0 = __expf(sacc[nt][hf * 2]     - mc);
                float p1 = __expf(sacc[nt][hf * 2 + 1] - mc);
                rs += p0 + p1;
                // P[lr][64] fp16, 128B rows: pair at col nt*8 + 2*l4
                *(uint32_t*)(sm + PS_OFF + lr * 128
                             + ((nt ^ (lr & 7)) << 4) + l4 * 4) = packh2(p0, p1);
            }
            rs += __shfl_xor_sync(0xffffffffu, rs, 1);
            rs += __shfl_xor_sync(0xffffffffu, rs, 2);
            lreg[hf] = lreg[hf] * corr + rs;
#pragma unroll
            for (int nt = 0; nt < 16; nt++) {
                oacc[nt][hf * 2]     *= corr;
                oacc[nt][hf * 2 + 1] *= corr;
            }
        }
        __syncwarp();   // P rows are warp-private

        // ---- O += P V : 16 rows x 128 d, k=64 (4 x k16) ----
        const uint32_t vb = sb + V_OFF(jt & 1);
#pragma unroll
        for (int ks = 0; ks < 4; ks++) {
            uint32_t a[4], b[8][4];
            ldsm4(a, sb + PS_OFF + swz(wid * 16 + arow_l, 2 * ks + asel, 128));
#pragma unroll
            for (int pr = 0; pr < 8; pr++)
                ldsm4(b[pr], vb + swz(pr * 16 + brow_l, 2 * ks + bsel, 128));
#pragma unroll
            for (int nt = 0; nt < 16; nt++)
                mma16(oacc[nt], a, &b[nt >> 1][(nt & 1) * 2]);
        }
    }

    // ---- finalize (fp16 for out-proj consumption) ----
    const int b = bh >> 3, h = bh & 7;
#pragma unroll
    for (int hf = 0; hf < 2; hf++) {
        float inv = 1.f / lreg[hf];
        int gi = i0 + wid * 16 + g + 8 * hf;
        size_t base = ((size_t)(b * NN + gi)) * 1024 + h * DH;
#pragma unroll
        for (int nt = 0; nt < 16; nt++)
            *(uint32_t*)(g_att + base + nt * 8 + 2 * l4) =
                packh2(oacc[nt][hf * 2] * inv, oacc[nt][hf * 2 + 1] * inv);
    }
}

// ---------------- launcher ----------------
extern "C" void kernel_launch(void* const* d_in, const int* in_sizes, int n_in,
                              void* d_out, int out_size)
{
    const float* x     = (const float*)d_in[0];
    const float* W_qkv = (const float*)d_in[1];
    const float* W_out = (const float*)d_in[2];
    const float* b_out = (const float*)d_in[3];
    const int*   mask  = (const int*)  d_in[4];
    float* out = (float*)d_out;

    cudaFuncSetAttribute(attn_kernel,
                         cudaFuncAttributeMaxDynamicSharedMemorySize, ATT_SMEM);
    cudaFuncSetAttribute(mma_gemm<0>,
                         cudaFuncAttributeMaxDynamicSharedMemorySize, GEMM_SMEM);
    cudaFuncSetAttribute(mma_gemm<1>,
                         cudaFuncAttributeMaxDynamicSharedMemorySize, GEMM_SMEM);

    __half* xh;    cudaGetSymbolAddress((void**)&xh, g_xh);
    __half* wqkvT; cudaGetSymbolAddress((void**)&wqkvT, g_wqkvT);
    __half* woutT; cudaGetSymbolAddress((void**)&woutT, g_woutT);
    __half* att;   cudaGetSymbolAddress((void**)&att, g_att);

    conv_x<<<4096, 256>>>(x, xh);
    transpose_k<<<dim3(96, 32), dim3(32, 8)>>>(W_qkv, wqkvT, 1024, 3072);
    transpose_k<<<dim3(32, 32), dim3(32, 8)>>>(W_out, woutT, 1024, 1024);

    mma_gemm<0><<<dim3(24, 64), 256, GEMM_SMEM>>>(xh, wqkvT, nullptr, nullptr);
    attn_kernel<<<dim3(32, 16), 256, ATT_SMEM>>>(mask);
    mma_gemm<1><<<dim3(8, 64), 256, GEMM_SMEM>>>(att, woutT, b_out, out);
}

// round 10
// speedup vs baseline: 2.0793x; 1.1347x over previous
#include <cuda_runtime.h>
#include <cuda_fp16.h>
#include <math.h>
#include <stdint.h>

#define NN 4096
#define HEADS 8
#define DH 128
#define MAXMASK 2048
#define ATT_SCALE 0.03125f  // 1024^-0.5 (2^-5, exact)

// ---------------- scratch (fp16 operands everywhere) ----------------
__device__ __half g_xh [(size_t)8192*1024];   // x in fp16
__device__ __half g_q  [(size_t)16*NN*DH];    // [bh][n][d], pre-scaled by 2^-5
__device__ __half g_k  [(size_t)16*NN*DH];    // [bh][n][d]
__device__ __half g_vT [(size_t)16*DH*NN];    // [bh][d][n]
__device__ __half g_att[(size_t)8192*1024];   // [b*n][dim]
__device__ __half g_wqkvT[(size_t)3072*1024]; // W_qkv^T fp16
__device__ __half g_woutT[(size_t)1024*1024]; // W_out^T fp16

// ---------------- helpers ----------------
__device__ __forceinline__ uint32_t smem_u32(const void* p) {
    uint32_t a;
    asm("{ .reg .u64 t; cvta.to.shared.u64 t, %1; cvt.u32.u64 %0, t; }"
        : "=r"(a) : "l"(p));
    return a;
}
__device__ __forceinline__ void cp16(uint32_t sdst, const void* gsrc) {
    asm volatile("cp.async.cg.shared.global [%0], [%1], 16;"
                 :: "r"(sdst), "l"(gsrc) : "memory");
}
#define CP_COMMIT() asm volatile("cp.async.commit_group;" ::: "memory")
#define CP_WAIT(n)  asm volatile("cp.async.wait_group %0;" :: "n"(n) : "memory")

__device__ __forceinline__ void ldsm4(uint32_t* r, uint32_t saddr) {
    asm volatile("ldmatrix.sync.aligned.m8n8.x4.shared.b16 {%0,%1,%2,%3}, [%4];"
        : "=r"(r[0]), "=r"(r[1]), "=r"(r[2]), "=r"(r[3]) : "r"(saddr));
}
__device__ __forceinline__ void mma16(float* d, const uint32_t* a, const uint32_t* b) {
    asm volatile(
        "mma.sync.aligned.m16n8k16.row.col.f32.f16.f16.f32 "
        "{%0,%1,%2,%3}, {%4,%5,%6,%7}, {%8,%9}, {%0,%1,%2,%3};"
        : "+f"(d[0]), "+f"(d[1]), "+f"(d[2]), "+f"(d[3])
        : "r"(a[0]), "r"(a[1]), "r"(a[2]), "r"(a[3]), "r"(b[0]), "r"(b[1]));
}
__device__ __forceinline__ uint32_t swz(int row, int slot, int rowb) {
    return (uint32_t)(row * rowb + ((slot ^ (row & 7)) << 4));
}
__device__ __forceinline__ uint32_t packh2(float a, float b) {
    __half2 h = __floats2half2_rn(a, b);
    return *(uint32_t*)&h;
}

// ---------------- convert x to fp16 ----------------
__global__ void conv_x(const float* __restrict__ in, __half* __restrict__ outp)
{
    size_t i = ((size_t)blockIdx.x * blockDim.x + threadIdx.x) * 8;
    float4 v0 = *(const float4*)(in + i);
    float4 v1 = *(const float4*)(in + i + 4);
    uint4 o;
    o.x = packh2(v0.x, v0.y); o.y = packh2(v0.z, v0.w);
    o.z = packh2(v1.x, v1.y); o.w = packh2(v1.z, v1.w);
    *(uint4*)(outp + i) = o;
}

// ---------------- weight transpose + fp16 convert ----------------
__global__ void transpose_k(const float* __restrict__ in, __half* __restrict__ outp,
                            int R, int C)
{
    __shared__ float t[32][33];
    int bx = blockIdx.x * 32, by = blockIdx.y * 32;
    int tx = threadIdx.x, ty = threadIdx.y;  // 32 x 8
#pragma unroll
    for (int i = 0; i < 32; i += 8)
        t[ty + i][tx] = in[(size_t)(by + ty + i) * C + bx + tx];
    __syncthreads();
#pragma unroll
    for (int i = 0; i < 32; i += 8)
        outp[(size_t)(bx + ty + i) * R + by + tx] = __float2half(t[tx][ty + i]);
}

// ================= fp16 GEMM: C[M x Ncols] = A[M x 1024] * Bt[Ncols x 1024]^T ==
#define GEMM_SMEM 65536
template<int MODE>
__global__ __launch_bounds__(256, 2) void mma_gemm(
    const __half* __restrict__ A, const __half* __restrict__ Bt,
    const float* __restrict__ bias, float* __restrict__ out)
{
    extern __shared__ char sm[];
    const uint32_t sb = smem_u32(sm);
    const int tid = threadIdx.x, lane = tid & 31, wid = tid >> 5;
    const int wm = wid >> 2, wn = wid & 3;
    const int g = lane >> 2, l4 = lane & 3;
    const int m0 = blockIdx.y * 128, col0 = blockIdx.x * 128;

    const int arow_l = lane & 15;
    const int asel = (lane >> 4) & 1;
    const int brow_l = (lane & 7) + ((lane >> 4) & 1) * 8;
    const int bsel = (lane >> 3) & 1;

    float acc[4][4][4];
#pragma unroll
    for (int mt = 0; mt < 4; mt++)
#pragma unroll
        for (int nt = 0; nt < 4; nt++)
#pragma unroll
            for (int r = 0; r < 4; r++) acc[mt][nt][r] = 0.f;

    auto fill = [&](int buf, int k0) {
#pragma unroll
        for (int i = 0; i < 2; i++) {
            int p = tid + i * 256;
            int r = p >> 2, s = (p & 3) * 2;
            cp16(sb + buf * 16384 + swz(r, s, 128),
                 A + (size_t)(m0 + r) * 1024 + k0 + s * 8);
            cp16(sb + buf * 16384 + swz(r, s + 1, 128),
                 A + (size_t)(m0 + r) * 1024 + k0 + s * 8 + 8);
        }
#pragma unroll
        for (int i = 0; i < 2; i++) {
            int p = tid + i * 256;
            int r = p >> 2, s = (p & 3) * 2;
            cp16(sb + 32768 + buf * 16384 + swz(r, s, 128),
                 Bt + (size_t)(col0 + r) * 1024 + k0 + s * 8);
            cp16(sb + 32768 + buf * 16384 + swz(r, s + 1, 128),
                 Bt + (size_t)(col0 + r) * 1024 + k0 + s * 8 + 8);
        }
    };

    fill(0, 0);
    CP_COMMIT();

    for (int kb = 0; kb < 16; kb++) {
        CP_WAIT(0);
        __syncthreads();
        if (kb < 15) { fill((kb + 1) & 1, (kb + 1) * 64); CP_COMMIT(); }
        const uint32_t ab = sb + (kb & 1) * 16384;
        const uint32_t bb = sb + 32768 + (kb & 1) * 16384;
#pragma unroll
        for (int ks = 0; ks < 4; ks++) {
            uint32_t a[4][4], b[2][4];
#pragma unroll
            for (int mt = 0; mt < 4; mt++) {
                int row = wm * 64 + mt * 16 + arow_l;
                ldsm4(a[mt], ab + swz(row, 2 * ks + asel, 128));
            }
#pragma unroll
            for (int pr = 0; pr < 2; pr++) {
                int row = wn * 32 + pr * 16 + brow_l;
                ldsm4(b[pr], bb + swz(row, 2 * ks + bsel, 128));
            }
#pragma unroll
            for (int mt = 0; mt < 4; mt++)
#pragma unroll
                for (int nt = 0; nt < 4; nt++)
                    mma16(acc[mt][nt], a[mt], &b[nt >> 1][(nt & 1) * 2]);
        }
    }

    if (MODE == 0) {
        const int which = col0 >> 10;          // 0=q 1=k 2=v
        const int h = (col0 & 1023) >> 7;
#pragma unroll
        for (int mt = 0; mt < 4; mt++)
#pragma unroll
            for (int nt = 0; nt < 4; nt++) {
                int col = col0 + wn * 32 + nt * 8 + 2 * l4;
                int dd = col & 127;
#pragma unroll
                for (int hf = 0; hf < 2; hf++) {
                    int gr = m0 + wm * 64 + mt * 16 + g + 8 * hf;
                    int bb2 = gr >> 12, n = gr & 4095;
                    int bh = bb2 * HEADS + h;
                    float c0 = acc[mt][nt][hf * 2], c1 = acc[mt][nt][hf * 2 + 1];
                    if (which == 0)     // pre-scale q by 2^-5 (exact)
                        *(uint32_t*)(g_q + ((size_t)bh * NN + n) * DH + dd) =
                            packh2(c0 * ATT_SCALE, c1 * ATT_SCALE);
                    else if (which == 1)
                        *(uint32_t*)(g_k + ((size_t)bh * NN + n) * DH + dd) = packh2(c0, c1);
                    else {
                        __half* dst = g_vT + ((size_t)bh * DH + dd) * NN + n;
                        dst[0] = __float2half(c0); dst[NN] = __float2half(c1);
                    }
                }
            }
    } else {
#pragma unroll
        for (int mt = 0; mt < 4; mt++)
#pragma unroll
            for (int nt = 0; nt < 4; nt++) {
                int col = col0 + wn * 32 + nt * 8 + 2 * l4;
                float2 bv = *(const float2*)(bias + col);
#pragma unroll
                for (int hf = 0; hf < 2; hf++) {
                    int gr = m0 + wm * 64 + mt * 16 + g + 8 * hf;
                    *(float2*)(out + (size_t)gr * 1024 + col) =
                        make_float2(acc[mt][nt][hf * 2] + bv.x,
                                    acc[mt][nt][hf * 2 + 1] + bv.y);
                }
            }
    }
}

// ================= Flash attention fp16: i-tile 64, 128 threads, 2 CTAs/SM ====
// 4 warps; warp w owns rows 16w..16w+15 for S and PV (same shapes as R8).
// Q: 64 x 256B = 16KB | K: 2 x (64 x 256B) = 32KB | V^T: 2 x (128 x 128B) = 32KB
// P: 64 x 128B = 8KB.  Total 88KB -> 2 CTAs/SM (176KB <= 227KB).
#define QS_OFF   0
#define K_OFF(b) (16384 + (b) * 16384)
#define V_OFF(b) (49152 + (b) * 16384)
#define PS_OFF   81920
#define ATT_SMEM 90112

__global__ __launch_bounds__(128, 2) void attn_kernel(const int* __restrict__ mask)
{
    extern __shared__ char sm[];
    const uint32_t sb = smem_u32(sm);

    const int tid = threadIdx.x, lane = tid & 31, wid = tid >> 5;
    const int g = lane >> 2, l4 = lane & 3;
    const int i0 = blockIdx.x * 64;
    const int bh = blockIdx.y;

    const __half* qP  = g_q  + (size_t)bh * NN * DH;
    const __half* kP  = g_k  + (size_t)bh * NN * DH;
    const __half* vTP = g_vT + (size_t)bh * DH * NN;

    const int arow_l = lane & 15;
    const int asel = (lane >> 4) & 1;
    const int brow_l = (lane & 7) + ((lane >> 4) & 1) * 8;
    const int bsel = (lane >> 3) & 1;

    auto fillK = [&](int buf, int j0) {           // 64 rows x 16 slots
#pragma unroll
        for (int i = 0; i < 8; i++) {
            int p = tid + i * 128;
            int r = p >> 4, s = p & 15;
            cp16(sb + K_OFF(buf) + swz(r, s, 256),
                 kP + (size_t)(j0 + r) * DH + s * 8);
        }
    };
    auto fillV = [&](int buf, int j0) {           // 128 d-rows x 8 slots
#pragma unroll
        for (int i = 0; i < 8; i++) {
            int p = tid + i * 128;
            int r = p >> 3, s = p & 7;
            cp16(sb + V_OFF(buf) + swz(r, s, 128),
                 vTP + (size_t)r * NN + j0 + s * 8);
        }
    };

    // Q fill: 64 rows x 16 slots
#pragma unroll
    for (int i = 0; i < 8; i++) {
        int p = tid + i * 128;
        int r = p >> 4, s = p & 15;
        cp16(sb + QS_OFF + swz(r, s, 256), qP + (size_t)(i0 + r) * DH + s * 8);
    }
    fillK(0, 0);
    fillV(0, 0);
    CP_COMMIT();

    float oacc[16][4];
#pragma unroll
    for (int nt = 0; nt < 16; nt++)
#pragma unroll
        for (int r = 0; r < 4; r++) oacc[nt][r] = 0.f;
    float mreg[2] = {-1e30f, -1e30f};
    float lreg[2] = {0.f, 0.f};

    for (int jt = 0; jt < 64; jt++) {
        const int j0 = jt * 64;
        CP_WAIT(0);
        __syncthreads();

        if (jt < 63) {
            fillK((jt + 1) & 1, j0 + 64);
            fillV((jt + 1) & 1, j0 + 64);
            CP_COMMIT();
        }

        // ---- S = (Q*2^-5) K^T : 16 rows x 64 j, k=128 (8 x k16) ----
        float sacc[8][4];
#pragma unroll
        for (int nt = 0; nt < 8; nt++)
#pragma unroll
            for (int r = 0; r < 4; r++) sacc[nt][r] = 0.f;

        const uint32_t kb = sb + K_OFF(jt & 1);
#pragma unroll
        for (int ks = 0; ks < 8; ks++) {
            uint32_t a[4], b[4][4];
            ldsm4(a, sb + QS_OFF + swz(wid * 16 + arow_l, 2 * ks + asel, 256));
#pragma unroll
            for (int pr = 0; pr < 4; pr++)
                ldsm4(b[pr], kb + swz(pr * 16 + brow_l, 2 * ks + bsel, 256));
#pragma unroll
            for (int nt = 0; nt < 8; nt++)
                mma16(sacc[nt], a, &b[nt >> 1][(nt & 1) * 2]);
        }

        // ---- mask (S already scaled via pre-scaled Q) ----
        if (i0 < MAXMASK && j0 < MAXMASK) {
#pragma unroll
            for (int hf = 0; hf < 2; hf++) {
                int gi = i0 + wid * 16 + g + 8 * hf;
                const int* mp = mask + (size_t)gi * MAXMASK + j0;
#pragma unroll
                for (int nt = 0; nt < 8; nt++) {
                    int2 mv = *(const int2*)(mp + nt * 8 + 2 * l4);
                    if (mv.x == 0) sacc[nt][hf * 2]     = -INFINITY;
                    if (mv.y == 0) sacc[nt][hf * 2 + 1] = -INFINITY;
                }
            }
        }

        // ---- softmax: fully in-warp ----
#pragma unroll
        for (int hf = 0; hf < 2; hf++) {
            int lr = wid * 16 + g + 8 * hf;
            float pm = -INFINITY;
#pragma unroll
            for (int nt = 0; nt < 8; nt++)
                pm = fmaxf(pm, fmaxf(sacc[nt][hf * 2], sacc[nt][hf * 2 + 1]));
            pm = fmaxf(pm, __shfl_xor_sync(0xffffffffu, pm, 1));
            pm = fmaxf(pm, __shfl_xor_sync(0xffffffffu, pm, 2));
            float mc = fmaxf(fmaxf(mreg[hf], pm), -1e30f);
            float corr = __expf(mreg[hf] - mc);
            mreg[hf] = mc;
            float rs = 0.f;
#pragma unroll
            for (int nt = 0; nt < 8; nt++) {
                float p0 = __expf(sacc[nt][hf * 2]     - mc);
                float p1 = __expf(sacc[nt][hf * 2 + 1] - mc);
                rs += p0 + p1;
                *(uint32_t*)(sm + PS_OFF + lr * 128
                             + ((nt ^ (lr & 7)) << 4) + l4 * 4) = packh2(p0, p1);
            }
            rs += __shfl_xor_sync(0xffffffffu, rs, 1);
            rs += __shfl_xor_sync(0xffffffffu, rs, 2);
            lreg[hf] = lreg[hf] * corr + rs;
            if (__any_sync(0xffffffffu, corr != 1.0f)) {
#pragma unroll
                for (int nt = 0; nt < 16; nt++) {
                    oacc[nt][hf * 2]     *= corr;
                    oacc[nt][hf * 2 + 1] *= corr;
                }
            }
        }
        __syncwarp();   // P rows are warp-private

        // ---- O += P V : 16 rows x 128 d, k=64 (4 x k16) ----
        const uint32_t vb = sb + V_OFF(jt & 1);
#pragma unroll
        for (int ks = 0; ks < 4; ks++) {
            uint32_t a[4], b[8][4];
            ldsm4(a, sb + PS_OFF + swz(wid * 16 + arow_l, 2 * ks + asel, 128));
#pragma unroll
            for (int pr = 0; pr < 8; pr++)
                ldsm4(b[pr], vb + swz(pr * 16 + brow_l, 2 * ks + bsel, 128));
#pragma unroll
            for (int nt = 0; nt < 16; nt++)
                mma16(oacc[nt], a, &b[nt >> 1][(nt & 1) * 2]);
        }
    }

    // ---- finalize (fp16 for out-proj consumption) ----
    const int b = bh >> 3, h = bh & 7;
#pragma unroll
    for (int hf = 0; hf < 2; hf++) {
        float inv = 1.f / lreg[hf];
        int gi = i0 + wid * 16 + g + 8 * hf;
        size_t base = ((size_t)(b * NN + gi)) * 1024 + h * DH;
#pragma unroll
        for (int nt = 0; nt < 16; nt++)
            *(uint32_t*)(g_att + base + nt * 8 + 2 * l4) =
                packh2(oacc[nt][hf * 2] * inv, oacc[nt][hf * 2 + 1] * inv);
    }
}

// ---------------- launcher ----------------
extern "C" void kernel_launch(void* const* d_in, const int* in_sizes, int n_in,
                              void* d_out, int out_size)
{
    const float* x     = (const float*)d_in[0];
    const float* W_qkv = (const float*)d_in[1];
    const float* W_out = (const float*)d_in[2];
    const float* b_out = (const float*)d_in[3];
    const int*   mask  = (const int*)  d_in[4];
    float* out = (float*)d_out;

    cudaFuncSetAttribute(attn_kernel,
                         cudaFuncAttributeMaxDynamicSharedMemorySize, ATT_SMEM);
    cudaFuncSetAttribute(mma_gemm<0>,
                         cudaFuncAttributeMaxDynamicSharedMemorySize, GEMM_SMEM);
    cudaFuncSetAttribute(mma_gemm<1>,
                         cudaFuncAttributeMaxDynamicSharedMemorySize, GEMM_SMEM);

    __half* xh;    cudaGetSymbolAddress((void**)&xh, g_xh);
    __half* wqkvT; cudaGetSymbolAddress((void**)&wqkvT, g_wqkvT);
    __half* woutT; cudaGetSymbolAddress((void**)&woutT, g_woutT);
    __half* att;   cudaGetSymbolAddress((void**)&att, g_att);

    conv_x<<<4096, 256>>>(x, xh);
    transpose_k<<<dim3(96, 32), dim3(32, 8)>>>(W_qkv, wqkvT, 1024, 3072);
    transpose_k<<<dim3(32, 32), dim3(32, 8)>>>(W_out, woutT, 1024, 1024);

    mma_gemm<0><<<dim3(24, 64), 256, GEMM_SMEM>>>(xh, wqkvT, nullptr, nullptr);
    attn_kernel<<<dim3(64, 16), 128, ATT_SMEM>>>(mask);
    mma_gemm<1><<<dim3(8, 64), 256, GEMM_SMEM>>>(att, woutT, b_out, out);
}

// round 11
// speedup vs baseline: 2.3065x; 1.1093x over previous
#include <cuda_runtime.h>
#include <cuda_fp16.h>
#include <math.h>
#include <stdint.h>

#define NN 4096
#define HEADS 8
#define DH 128
#define MAXMASK 2048
// attention scale folded with log2(e): softmax done in exp2 domain
#define ATT_SCALE_L2 (0.03125f * 1.44269504f)

// ---------------- scratch (fp16 operands everywhere) ----------------
__device__ __half g_xh [(size_t)8192*1024];   // x in fp16
__device__ __half g_q  [(size_t)16*NN*DH];    // [bh][n][d], pre-scaled by 2^-5*log2e
__device__ __half g_k  [(size_t)16*NN*DH];    // [bh][n][d]
__device__ __half g_vT [(size_t)16*DH*NN];    // [bh][d][n]
__device__ __half g_att[(size_t)8192*1024];   // [b*n][dim]
__device__ __half g_wqkvT[(size_t)3072*1024]; // W_qkv^T fp16
__device__ __half g_woutT[(size_t)1024*1024]; // W_out^T fp16

// ---------------- helpers ----------------
__device__ __forceinline__ uint32_t smem_u32(const void* p) {
    uint32_t a;
    asm("{ .reg .u64 t; cvta.to.shared.u64 t, %1; cvt.u32.u64 %0, t; }"
        : "=r"(a) : "l"(p));
    return a;
}
__device__ __forceinline__ void cp16(uint32_t sdst, const void* gsrc) {
    asm volatile("cp.async.cg.shared.global [%0], [%1], 16;"
                 :: "r"(sdst), "l"(gsrc) : "memory");
}
#define CP_COMMIT() asm volatile("cp.async.commit_group;" ::: "memory")
#define CP_WAIT(n)  asm volatile("cp.async.wait_group %0;" :: "n"(n) : "memory")

__device__ __forceinline__ void ldsm4(uint32_t* r, uint32_t saddr) {
    asm volatile("ldmatrix.sync.aligned.m8n8.x4.shared.b16 {%0,%1,%2,%3}, [%4];"
        : "=r"(r[0]), "=r"(r[1]), "=r"(r[2]), "=r"(r[3]) : "r"(saddr));
}
__device__ __forceinline__ void mma16(float* d, const uint32_t* a, const uint32_t* b) {
    asm volatile(
        "mma.sync.aligned.m16n8k16.row.col.f32.f16.f16.f32 "
        "{%0,%1,%2,%3}, {%4,%5,%6,%7}, {%8,%9}, {%0,%1,%2,%3};"
        : "+f"(d[0]), "+f"(d[1]), "+f"(d[2]), "+f"(d[3])
        : "r"(a[0]), "r"(a[1]), "r"(a[2]), "r"(a[3]), "r"(b[0]), "r"(b[1]));
}
__device__ __forceinline__ uint32_t swz(int row, int slot, int rowb) {
    return (uint32_t)(row * rowb + ((slot ^ (row & 7)) << 4));
}
__device__ __forceinline__ uint32_t packh2(float a, float b) {
    __half2 h = __floats2half2_rn(a, b);
    return *(uint32_t*)&h;
}
__device__ __forceinline__ float ex2f(float x) {
    float r;
    asm("ex2.approx.ftz.f32 %0, %1;" : "=f"(r) : "f"(x));
    return r;
}

// ---------------- convert x to fp16 ----------------
__global__ void conv_x(const float* __restrict__ in, __half* __restrict__ outp)
{
    size_t i = ((size_t)blockIdx.x * blockDim.x + threadIdx.x) * 8;
    float4 v0 = *(const float4*)(in + i);
    float4 v1 = *(const float4*)(in + i + 4);
    uint4 o;
    o.x = packh2(v0.x, v0.y); o.y = packh2(v0.z, v0.w);
    o.z = packh2(v1.x, v1.y); o.w = packh2(v1.z, v1.w);
    *(uint4*)(outp + i) = o;
}

// ---------------- weight transpose + fp16 convert ----------------
__global__ void transpose_k(const float* __restrict__ in, __half* __restrict__ outp,
                            int R, int C)
{
    __shared__ float t[32][33];
    int bx = blockIdx.x * 32, by = blockIdx.y * 32;
    int tx = threadIdx.x, ty = threadIdx.y;  // 32 x 8
#pragma unroll
    for (int i = 0; i < 32; i += 8)
        t[ty + i][tx] = in[(size_t)(by + ty + i) * C + bx + tx];
    __syncthreads();
#pragma unroll
    for (int i = 0; i < 32; i += 8)
        outp[(size_t)(bx + ty + i) * R + by + tx] = __float2half(t[tx][ty + i]);
}

// ================= fp16 GEMM: C[M x Ncols] = A[M x 1024] * Bt[Ncols x 1024]^T ==
#define GEMM_SMEM 65536
template<int MODE>
__global__ __launch_bounds__(256, 2) void mma_gemm(
    const __half* __restrict__ A, const __half* __restrict__ Bt,
    const float* __restrict__ bias, float* __restrict__ out)
{
    extern __shared__ char sm[];
    const uint32_t sb = smem_u32(sm);
    const int tid = threadIdx.x, lane = tid & 31, wid = tid >> 5;
    const int wm = wid >> 2, wn = wid & 3;
    const int g = lane >> 2, l4 = lane & 3;
    const int m0 = blockIdx.y * 128, col0 = blockIdx.x * 128;

    const int arow_l = lane & 15;
    const int asel = (lane >> 4) & 1;
    const int brow_l = (lane & 7) + ((lane >> 4) & 1) * 8;
    const int bsel = (lane >> 3) & 1;

    float acc[4][4][4];
#pragma unroll
    for (int mt = 0; mt < 4; mt++)
#pragma unroll
        for (int nt = 0; nt < 4; nt++)
#pragma unroll
            for (int r = 0; r < 4; r++) acc[mt][nt][r] = 0.f;

    auto fill = [&](int buf, int k0) {
#pragma unroll
        for (int i = 0; i < 2; i++) {
            int p = tid + i * 256;
            int r = p >> 2, s = (p & 3) * 2;
            cp16(sb + buf * 16384 + swz(r, s, 128),
                 A + (size_t)(m0 + r) * 1024 + k0 + s * 8);
            cp16(sb + buf * 16384 + swz(r, s + 1, 128),
                 A + (size_t)(m0 + r) * 1024 + k0 + s * 8 + 8);
        }
#pragma unroll
        for (int i = 0; i < 2; i++) {
            int p = tid + i * 256;
            int r = p >> 2, s = (p & 3) * 2;
            cp16(sb + 32768 + buf * 16384 + swz(r, s, 128),
                 Bt + (size_t)(col0 + r) * 1024 + k0 + s * 8);
            cp16(sb + 32768 + buf * 16384 + swz(r, s + 1, 128),
                 Bt + (size_t)(col0 + r) * 1024 + k0 + s * 8 + 8);
        }
    };

    fill(0, 0);
    CP_COMMIT();

    for (int kb = 0; kb < 16; kb++) {
        CP_WAIT(0);
        __syncthreads();
        if (kb < 15) { fill((kb + 1) & 1, (kb + 1) * 64); CP_COMMIT(); }
        const uint32_t ab = sb + (kb & 1) * 16384;
        const uint32_t bb = sb + 32768 + (kb & 1) * 16384;
#pragma unroll
        for (int ks = 0; ks < 4; ks++) {
            uint32_t a[4][4], b[2][4];
#pragma unroll
            for (int mt = 0; mt < 4; mt++) {
                int row = wm * 64 + mt * 16 + arow_l;
                ldsm4(a[mt], ab + swz(row, 2 * ks + asel, 128));
            }
#pragma unroll
            for (int pr = 0; pr < 2; pr++) {
                int row = wn * 32 + pr * 16 + brow_l;
                ldsm4(b[pr], bb + swz(row, 2 * ks + bsel, 128));
            }
#pragma unroll
            for (int mt = 0; mt < 4; mt++)
#pragma unroll
                for (int nt = 0; nt < 4; nt++)
                    mma16(acc[mt][nt], a[mt], &b[nt >> 1][(nt & 1) * 2]);
        }
    }

    if (MODE == 0) {
        const int which = col0 >> 10;          // 0=q 1=k 2=v
        const int h = (col0 & 1023) >> 7;
#pragma unroll
        for (int mt = 0; mt < 4; mt++)
#pragma unroll
            for (int nt = 0; nt < 4; nt++) {
                int col = col0 + wn * 32 + nt * 8 + 2 * l4;
                int dd = col & 127;
#pragma unroll
                for (int hf = 0; hf < 2; hf++) {
                    int gr = m0 + wm * 64 + mt * 16 + g + 8 * hf;
                    int bb2 = gr >> 12, n = gr & 4095;
                    int bh = bb2 * HEADS + h;
                    float c0 = acc[mt][nt][hf * 2], c1 = acc[mt][nt][hf * 2 + 1];
                    if (which == 0)     // pre-scale q by 2^-5 * log2(e)
                        *(uint32_t*)(g_q + ((size_t)bh * NN + n) * DH + dd) =
                            packh2(c0 * ATT_SCALE_L2, c1 * ATT_SCALE_L2);
                    else if (which == 1)
                        *(uint32_t*)(g_k + ((size_t)bh * NN + n) * DH + dd) = packh2(c0, c1);
                    else {
                        __half* dst = g_vT + ((size_t)bh * DH + dd) * NN + n;
                        dst[0] = __float2half(c0); dst[NN] = __float2half(c1);
                    }
                }
            }
    } else {
#pragma unroll
        for (int mt = 0; mt < 4; mt++)
#pragma unroll
            for (int nt = 0; nt < 4; nt++) {
                int col = col0 + wn * 32 + nt * 8 + 2 * l4;
                float2 bv = *(const float2*)(bias + col);
#pragma unroll
                for (int hf = 0; hf < 2; hf++) {
                    int gr = m0 + wm * 64 + mt * 16 + g + 8 * hf;
                    *(float2*)(out + (size_t)gr * 1024 + col) =
                        make_float2(acc[mt][nt][hf * 2] + bv.x,
                                    acc[mt][nt][hf * 2 + 1] + bv.y);
                }
            }
    }
}

// ================= Flash attention fp16 v4 ====================================
// i-tile 64, 128 threads (4 warps), 2 CTAs/SM. Warp w owns rows 16w..16w+15.
// Q fragments resident in registers; P passed register-direct (C-frag == A-frag);
// softmax in exp2 domain (scale*log2e folded into Q).
// Q: 64 x 256B = 16KB | K: 2 x 16KB | V^T: 2 x 16KB.  Total 80KB -> 2 CTAs/SM.
#define QS_OFF   0
#define K_OFF(b) (16384 + (b) * 16384)
#define V_OFF(b) (49152 + (b) * 16384)
#define ATT_SMEM 81920

__global__ __launch_bounds__(128, 2) void attn_kernel(const int* __restrict__ mask)
{
    extern __shared__ char sm[];
    const uint32_t sb = smem_u32(sm);

    const int tid = threadIdx.x, lane = tid & 31, wid = tid >> 5;
    const int g = lane >> 2, l4 = lane & 3;
    const int i0 = blockIdx.x * 64;
    const int bh = blockIdx.y;

    const __half* qP  = g_q  + (size_t)bh * NN * DH;
    const __half* kP  = g_k  + (size_t)bh * NN * DH;
    const __half* vTP = g_vT + (size_t)bh * DH * NN;

    const int arow_l = lane & 15;
    const int asel = (lane >> 4) & 1;
    const int brow_l = (lane & 7) + ((lane >> 4) & 1) * 8;
    const int bsel = (lane >> 3) & 1;

    auto fillK = [&](int buf, int j0) {           // 64 rows x 16 slots
#pragma unroll
        for (int i = 0; i < 8; i++) {
            int p = tid + i * 128;
            int r = p >> 4, s = p & 15;
            cp16(sb + K_OFF(buf) + swz(r, s, 256),
                 kP + (size_t)(j0 + r) * DH + s * 8);
        }
    };
    auto fillV = [&](int buf, int j0) {           // 128 d-rows x 8 slots
#pragma unroll
        for (int i = 0; i < 8; i++) {
            int p = tid + i * 128;
            int r = p >> 3, s = p & 7;
            cp16(sb + V_OFF(buf) + swz(r, s, 128),
                 vTP + (size_t)r * NN + j0 + s * 8);
        }
    };

    // Q fill: 64 rows x 16 slots
#pragma unroll
    for (int i = 0; i < 8; i++) {
        int p = tid + i * 128;
        int r = p >> 4, s = p & 15;
        cp16(sb + QS_OFF + swz(r, s, 256), qP + (size_t)(i0 + r) * DH + s * 8);
    }
    fillK(0, 0);
    fillV(0, 0);
    CP_COMMIT();

    uint32_t qf[8][4];   // Q fragments, resident for whole kernel
    float oacc[16][4];
#pragma unroll
    for (int nt = 0; nt < 16; nt++)
#pragma unroll
        for (int r = 0; r < 4; r++) oacc[nt][r] = 0.f;
    float mreg[2] = {-1e30f, -1e30f};
    float lreg[2] = {0.f, 0.f};

    for (int jt = 0; jt < 64; jt++) {
        const int j0 = jt * 64;
        CP_WAIT(0);
        __syncthreads();

        if (jt == 0) {   // one-time: hoist Q fragments to registers
#pragma unroll
            for (int ks = 0; ks < 8; ks++)
                ldsm4(qf[ks], sb + QS_OFF + swz(wid * 16 + arow_l, 2 * ks + asel, 256));
        }
        if (jt < 63) {
            fillK((jt + 1) & 1, j0 + 64);
            fillV((jt + 1) & 1, j0 + 64);
            CP_COMMIT();
        }

        // ---- S = (Q*2^-5*log2e) K^T : 16 rows x 64 j, k=128 (8 x k16) ----
        float sacc[8][4];
#pragma unroll
        for (int nt = 0; nt < 8; nt++)
#pragma unroll
            for (int r = 0; r < 4; r++) sacc[nt][r] = 0.f;

        const uint32_t kb = sb + K_OFF(jt & 1);
#pragma unroll
        for (int ks = 0; ks < 8; ks++) {
            uint32_t b[4][4];
#pragma unroll
            for (int pr = 0; pr < 4; pr++)
                ldsm4(b[pr], kb + swz(pr * 16 + brow_l, 2 * ks + bsel, 256));
#pragma unroll
            for (int nt = 0; nt < 8; nt++)
                mma16(sacc[nt], qf[ks], &b[nt >> 1][(nt & 1) * 2]);
        }

        // ---- mask (S already in log2 domain) ----
        if (i0 < MAXMASK && j0 < MAXMASK) {
#pragma unroll
            for (int hf = 0; hf < 2; hf++) {
                int gi = i0 + wid * 16 + g + 8 * hf;
                const int* mp = mask + (size_t)gi * MAXMASK + j0;
#pragma unroll
                for (int nt = 0; nt < 8; nt++) {
                    int2 mv = *(const int2*)(mp + nt * 8 + 2 * l4);
                    if (mv.x == 0) sacc[nt][hf * 2]     = -INFINITY;
                    if (mv.y == 0) sacc[nt][hf * 2 + 1] = -INFINITY;
                }
            }
        }

        // ---- softmax (exp2 domain), P stays in registers ----
#pragma unroll
        for (int hf = 0; hf < 2; hf++) {
            float pm = -INFINITY;
#pragma unroll
            for (int nt = 0; nt < 8; nt++)
                pm = fmaxf(pm, fmaxf(sacc[nt][hf * 2], sacc[nt][hf * 2 + 1]));
            pm = fmaxf(pm, __shfl_xor_sync(0xffffffffu, pm, 1));
            pm = fmaxf(pm, __shfl_xor_sync(0xffffffffu, pm, 2));
            float mc = fmaxf(fmaxf(mreg[hf], pm), -1e30f);
            float corr = ex2f(mreg[hf] - mc);
            mreg[hf] = mc;
            float rs = 0.f;
#pragma unroll
            for (int nt = 0; nt < 8; nt++) {
                float p0 = ex2f(sacc[nt][hf * 2]     - mc);
                float p1 = ex2f(sacc[nt][hf * 2 + 1] - mc);
                sacc[nt][hf * 2] = p0; sacc[nt][hf * 2 + 1] = p1;
                rs += p0 + p1;
            }
            rs += __shfl_xor_sync(0xffffffffu, rs, 1);
            rs += __shfl_xor_sync(0xffffffffu, rs, 2);
            lreg[hf] = lreg[hf] * corr + rs;
            if (__any_sync(0xffffffffu, corr != 1.0f)) {
#pragma unroll
                for (int nt = 0; nt < 16; nt++) {
                    oacc[nt][hf * 2]     *= corr;
                    oacc[nt][hf * 2 + 1] *= corr;
                }
            }
        }

        // ---- P C-fragments -> A-fragments (pure register pack) ----
        uint32_t pa[4][4];
#pragma unroll
        for (int ks2 = 0; ks2 < 4; ks2++) {
            pa[ks2][0] = packh2(sacc[2 * ks2][0],     sacc[2 * ks2][1]);
            pa[ks2][1] = packh2(sacc[2 * ks2][2],     sacc[2 * ks2][3]);
            pa[ks2][2] = packh2(sacc[2 * ks2 + 1][0], sacc[2 * ks2 + 1][1]);
            pa[ks2][3] = packh2(sacc[2 * ks2 + 1][2], sacc[2 * ks2 + 1][3]);
        }

        // ---- O += P V : 16 rows x 128 d, k=64 (4 x k16) ----
        const uint32_t vb = sb + V_OFF(jt & 1);
#pragma unroll
        for (int ks2 = 0; ks2 < 4; ks2++) {
            uint32_t b[8][4];
#pragma unroll
            for (int pr = 0; pr < 8; pr++)
                ldsm4(b[pr], vb + swz(pr * 16 + brow_l, 2 * ks2 + bsel, 128));
#pragma unroll
            for (int nt = 0; nt < 16; nt++)
                mma16(oacc[nt], pa[ks2], &b[nt >> 1][(nt & 1) * 2]);
        }
    }

    // ---- finalize (fp16 for out-proj consumption) ----
    const int b = bh >> 3, h = bh & 7;
#pragma unroll
    for (int hf = 0; hf < 2; hf++) {
        float inv = 1.f / lreg[hf];
        int gi = i0 + wid * 16 + g + 8 * hf;
        size_t base = ((size_t)(b * NN + gi)) * 1024 + h * DH;
#pragma unroll
        for (int nt = 0; nt < 16; nt++)
            *(uint32_t*)(g_att + base + nt * 8 + 2 * l4) =
                packh2(oacc[nt][hf * 2] * inv, oacc[nt][hf * 2 + 1] * inv);
    }
}

// ---------------- launcher ----------------
extern "C" void kernel_launch(void* const* d_in, const int* in_sizes, int n_in,
                              void* d_out, int out_size)
{
    const float* x     = (const float*)d_in[0];
    const float* W_qkv = (const float*)d_in[1];
    const float* W_out = (const float*)d_in[2];
    const float* b_out = (const float*)d_in[3];
    const int*   mask  = (const int*)  d_in[4];
    float* out = (float*)d_out;

    cudaFuncSetAttribute(attn_kernel,
                         cudaFuncAttributeMaxDynamicSharedMemorySize, ATT_SMEM);
    cudaFuncSetAttribute(mma_gemm<0>,
                         cudaFuncAttributeMaxDynamicSharedMemorySize, GEMM_SMEM);
    cudaFuncSetAttribute(mma_gemm<1>,
                         cudaFuncAttributeMaxDynamicSharedMemorySize, GEMM_SMEM);

    __half* xh;    cudaGetSymbolAddress((void**)&xh, g_xh);
    __half* wqkvT; cudaGetSymbolAddress((void**)&wqkvT, g_wqkvT);
    __half* woutT; cudaGetSymbolAddress((void**)&woutT, g_woutT);
    __half* att;   cudaGetSymbolAddress((void**)&att, g_att);

    conv_x<<<4096, 256>>>(x, xh);
    transpose_k<<<dim3(96, 32), dim3(32, 8)>>>(W_qkv, wqkvT, 1024, 3072);
    transpose_k<<<dim3(32, 32), dim3(32, 8)>>>(W_out, woutT, 1024, 1024);

    mma_gemm<0><<<dim3(24, 64), 256, GEMM_SMEM>>>(xh, wqkvT, nullptr, nullptr);
    attn_kernel<<<dim3(64, 16), 128, ATT_SMEM>>>(mask);
    mma_gemm<1><<<dim3(8, 64), 256, GEMM_SMEM>>>(att, woutT, b_out, out);
}